// round 2
// baseline (speedup 1.0000x reference)
#include <cuda_runtime.h>
#include <math.h>

#define NMAX 50000
#define EMAX 800000
#define ETOTAL (EMAX + NMAX)
#define IN_DIM 256
#define HID 64
#define L1C 256
#define OUTD 64

// ---------------- scratch (device globals; allocation-free) ----------------
__device__ float g_xl1[(size_t)NMAX * L1C];   // layer1 xl  (51.2 MB)
__device__ float g_xr1[(size_t)NMAX * L1C];   // layer1 xr; reused for layer2 xl2/xr2
__device__ float g_h[(size_t)NMAX * HID];     // hidden after LN+ReLU
__device__ int   g_deg[NMAX + 1];
__device__ int   g_off[NMAX + 1];
__device__ int   g_cur[NMAX];
__device__ int   g_src[ETOTAL];

// ---------------- CSR build ----------------
__global__ void zero_deg_kernel(int n) {
    int i = blockIdx.x * blockDim.x + threadIdx.x;
    if (i <= n) g_deg[i] = 0;
}

__global__ void hist_kernel(const int* __restrict__ ei, int E, int n) {
    int e = blockIdx.x * blockDim.x + threadIdx.x;
    int tot = E + n;
    if (e < tot) {
        int d = (e < E) ? ei[E + e] : (e - E);
        if (d < 0) d = 0;
        if (d >= n) d = n - 1;
        atomicAdd(&g_deg[d], 1);
    }
}

__global__ void scan_kernel(int n) {
    __shared__ int partial[1024];
    int tid = threadIdx.x;
    int CH = (n + 1023) / 1024;
    int base = tid * CH;
    int s = 0;
    for (int i = 0; i < CH; i++) {
        int idx = base + i;
        if (idx < n) s += g_deg[idx];
    }
    partial[tid] = s;
    __syncthreads();
    for (int d = 1; d < 1024; d <<= 1) {
        int v = partial[tid];
        int add = (tid >= d) ? partial[tid - d] : 0;
        __syncthreads();
        partial[tid] = v + add;
        __syncthreads();
    }
    int run = (tid == 0) ? 0 : partial[tid - 1];
    for (int i = 0; i < CH; i++) {
        int idx = base + i;
        if (idx < n) {
            g_off[idx] = run;
            g_cur[idx] = run;
            run += g_deg[idx];
        }
    }
    if (tid == 0) g_off[n] = partial[1023];
}

__global__ void scatter_kernel(const int* __restrict__ ei, int E, int n) {
    int e = blockIdx.x * blockDim.x + threadIdx.x;
    int tot = E + n;
    if (e < tot) {
        int s, d;
        if (e < E) { s = ei[e]; d = ei[E + e]; }
        else       { s = d = e - E; }
        if (s < 0) s = 0; if (s >= n) s = n - 1;
        if (d < 0) d = 0; if (d >= n) d = n - 1;
        int pos = atomicAdd(&g_cur[d], 1);
        if (pos >= 0 && pos < ETOTAL) g_src[pos] = s;
    }
}

// ---------------- SGEMM: C[M,N] = A[M,K] * B[K,N], row-major ----------------
// BM=64, BN=64, BK=8, 256 threads, 4x4 per thread. N % 64 == 0, K % 8 == 0.
__global__ void sgemm_kernel(const float* __restrict__ A, const float* __restrict__ B,
                             float* __restrict__ C, int M, int N, int K) {
    const int BK = 8;
    __shared__ float As[BK][64];
    __shared__ float Bs[BK][64];
    int tid = threadIdx.x;
    int rowBase = blockIdx.y * 64;
    int colBase = blockIdx.x * 64;
    int tm = tid >> 4;            // 0..15
    int tn = tid & 15;            // 0..15
    float acc[4][4] = {};

    int aRow = tid >> 2;          // 0..63
    int aK = (tid & 3) * 2;       // 0,2,4,6
    int bK = tid >> 5;            // 0..7
    int bN = (tid & 31) * 2;      // 0..62

    for (int k0 = 0; k0 < K; k0 += BK) {
        float2 av = make_float2(0.f, 0.f);
        int gr = rowBase + aRow;
        if (gr < M) av = *(const float2*)&A[(size_t)gr * K + k0 + aK];
        As[aK][aRow] = av.x;
        As[aK + 1][aRow] = av.y;
        float2 bv = *(const float2*)&B[(size_t)(k0 + bK) * N + colBase + bN];
        Bs[bK][bN] = bv.x;
        Bs[bK][bN + 1] = bv.y;
        __syncthreads();
#pragma unroll
        for (int kk = 0; kk < BK; kk++) {
            float a[4], b[4];
#pragma unroll
            for (int i = 0; i < 4; i++) a[i] = As[kk][tm * 4 + i];
#pragma unroll
            for (int j = 0; j < 4; j++) b[j] = Bs[kk][tn * 4 + j];
#pragma unroll
            for (int i = 0; i < 4; i++)
#pragma unroll
                for (int j = 0; j < 4; j++) acc[i][j] += a[i] * b[j];
        }
        __syncthreads();
    }
#pragma unroll
    for (int i = 0; i < 4; i++) {
        int r = rowBase + tm * 4 + i;
        if (r < M) {
#pragma unroll
            for (int j = 0; j < 4; j++)
                C[(size_t)r * N + colBase + tn * 4 + j] = acc[i][j];
        }
    }
}

// ---------------- Layer 1 GAT: warp h = head h, lane handles 2 channels ----
// block = 128 threads = 4 warps, one dst node per block.
__global__ void gat1_kernel(const float* __restrict__ att1, const float* __restrict__ b1,
                            const float* __restrict__ lng, const float* __restrict__ lnb,
                            int Nn) {
    int i = blockIdx.x;
    int t = threadIdx.x;          // 0..127
    int h = t >> 5;               // warp = head 0..3
    int l = t & 31;
    __shared__ float sout[256];
    __shared__ float red[4];
    __shared__ float red2[4];

    float2 xr = ((const float2*)(g_xr1 + (size_t)i * L1C + h * 64))[l];
    float2 at = ((const float2*)att1)[h * 32 + l];
    float acc0 = 0.f, acc1 = 0.f, den = 0.f;
    int e0 = g_off[i], e1 = g_off[i + 1];
    for (int e = e0; e < e1; e++) {
        int j = g_src[e];
        float2 xl = ((const float2*)(g_xl1 + (size_t)j * L1C + h * 64))[l];
        float s0 = xl.x + xr.x; s0 = s0 > 0.f ? s0 : 0.2f * s0;
        float s1 = xl.y + xr.y; s1 = s1 > 0.f ? s1 : 0.2f * s1;
        float term = s0 * at.x + s1 * at.y;
#pragma unroll
        for (int o = 16; o; o >>= 1) term += __shfl_xor_sync(0xffffffffu, term, o);
        float a = expf(term);
        acc0 += a * xl.x; acc1 += a * xl.y; den += a;
    }
    float inv = 1.f / (den + 1e-16f);
    sout[h * 64 + 2 * l]     = acc0 * inv;
    sout[h * 64 + 2 * l + 1] = acc1 * inv;
    __syncthreads();

    // heads mean + bias (threads t<64 carry data)
    float val = 0.f;
    if (t < 64)
        val = 0.25f * (sout[t] + sout[t + 64] + sout[t + 128] + sout[t + 192]) + b1[t];

    // LayerNorm over 64 values
    float v = (t < 64) ? val : 0.f;
#pragma unroll
    for (int o = 16; o; o >>= 1) v += __shfl_xor_sync(0xffffffffu, v, o);
    if (l == 0) red[h] = v;
    __syncthreads();
    float mu = (red[0] + red[1] + red[2] + red[3]) * (1.f / 64.f);
    float dd = (t < 64) ? (val - mu) : 0.f;
    float v2 = dd * dd;
#pragma unroll
    for (int o = 16; o; o >>= 1) v2 += __shfl_xor_sync(0xffffffffu, v2, o);
    if (l == 0) red2[h] = v2;
    __syncthreads();
    float var = (red2[0] + red2[1] + red2[2] + red2[3]) * (1.f / 64.f);
    if (t < 64) {
        float y = dd * rsqrtf(var + 1e-5f) * lng[t] + lnb[t];
        g_h[(size_t)i * HID + t] = fmaxf(y, 0.f);
    }
}

// ---------------- Layer 2 GAT: warp per node, 1 head, LN fused, -> d_out ----
// block = 128 threads = 4 warps = 4 nodes.
__global__ void gat2_kernel(const float* __restrict__ att2, const float* __restrict__ b2,
                            const float* __restrict__ lng, const float* __restrict__ lnb,
                            float* __restrict__ out, int Nn) {
    int w = threadIdx.x >> 5, l = threadIdx.x & 31;
    int i = blockIdx.x * 4 + w;
    if (i >= Nn) return;
    const float* xl2 = g_xr1;                               // overlay
    const float* xr2 = g_xr1 + (size_t)NMAX * OUTD;         // overlay

    float2 xr = ((const float2*)(xr2 + (size_t)i * OUTD))[l];
    float2 at = ((const float2*)att2)[l];
    float acc0 = 0.f, acc1 = 0.f, den = 0.f;
    int e0 = g_off[i], e1 = g_off[i + 1];
    for (int e = e0; e < e1; e++) {
        int j = g_src[e];
        float2 xl = ((const float2*)(xl2 + (size_t)j * OUTD))[l];
        float s0 = xl.x + xr.x; s0 = s0 > 0.f ? s0 : 0.2f * s0;
        float s1 = xl.y + xr.y; s1 = s1 > 0.f ? s1 : 0.2f * s1;
        float term = s0 * at.x + s1 * at.y;
#pragma unroll
        for (int o = 16; o; o >>= 1) term += __shfl_xor_sync(0xffffffffu, term, o);
        float a = expf(term);
        acc0 += a * xl.x; acc1 += a * xl.y; den += a;
    }
    float inv = 1.f / (den + 1e-16f);
    float2 bb = ((const float2*)b2)[l];
    float v0 = acc0 * inv + bb.x;
    float v1 = acc1 * inv + bb.y;

    // LayerNorm over 64 values within the warp
    float s = v0 + v1;
#pragma unroll
    for (int o = 16; o; o >>= 1) s += __shfl_xor_sync(0xffffffffu, s, o);
    float mu = s * (1.f / 64.f);
    float d0 = v0 - mu, d1 = v1 - mu;
    float q = d0 * d0 + d1 * d1;
#pragma unroll
    for (int o = 16; o; o >>= 1) q += __shfl_xor_sync(0xffffffffu, q, o);
    float var = q * (1.f / 64.f);
    float r = rsqrtf(var + 1e-5f);
    float2 gg = ((const float2*)lng)[l];
    float2 bn = ((const float2*)lnb)[l];
    float2 o2;
    o2.x = d0 * r * gg.x + bn.x;
    o2.y = d1 * r * gg.y + bn.y;
    ((float2*)(out + (size_t)i * OUTD))[l] = o2;
}

// ---------------- launch ----------------
extern "C" void kernel_launch(void* const* d_in, const int* in_sizes, int n_in,
                              void* d_out, int out_size) {
    const float* x    = (const float*)d_in[0];
    const int*   ei   = (const int*)d_in[1];
    const float* W1l  = (const float*)d_in[2];
    const float* W1r  = (const float*)d_in[3];
    const float* att1 = (const float*)d_in[4];
    const float* b1   = (const float*)d_in[5];
    const float* ln1g = (const float*)d_in[6];
    const float* ln1b = (const float*)d_in[7];
    const float* W2l  = (const float*)d_in[8];
    const float* W2r  = (const float*)d_in[9];
    const float* att2 = (const float*)d_in[10];
    const float* b2   = (const float*)d_in[11];
    const float* ln2g = (const float*)d_in[12];
    const float* ln2b = (const float*)d_in[13];
    float* out = (float*)d_out;

    int N = in_sizes[0] / IN_DIM;
    int E = in_sizes[1] / 2;
    if (N > NMAX) N = NMAX;
    if (E > EMAX) E = EMAX;
    int ETOT_RT = E + N;

    // Resolve device-symbol addresses (host shadows are NOT device pointers!)
    float *p_xl1, *p_xr1, *p_h;
    cudaGetSymbolAddress((void**)&p_xl1, g_xl1);
    cudaGetSymbolAddress((void**)&p_xr1, g_xr1);
    cudaGetSymbolAddress((void**)&p_h,   g_h);
    float* p_xl2 = p_xr1;                              // overlay for layer 2
    float* p_xr2 = p_xr1 + (size_t)NMAX * OUTD;

    // CSR build
    zero_deg_kernel<<<(N + 256) / 256, 256>>>(N);
    hist_kernel<<<(ETOT_RT + 255) / 256, 256>>>(ei, E, N);
    scan_kernel<<<1, 1024>>>(N);
    scatter_kernel<<<(ETOT_RT + 255) / 256, 256>>>(ei, E, N);

    // Layer 1 GEMMs: [N,256] x [256,256]
    {
        dim3 grid(L1C / 64, (N + 63) / 64);
        sgemm_kernel<<<grid, 256>>>(x, W1l, p_xl1, N, L1C, IN_DIM);
        sgemm_kernel<<<grid, 256>>>(x, W1r, p_xr1, N, L1C, IN_DIM);
    }

    // Layer 1 edge + softmax + aggregate + heads-mean + bias + LN + ReLU
    gat1_kernel<<<N, 128>>>(att1, b1, ln1g, ln1b, N);

    // Layer 2 GEMMs: [N,64] x [64,64]  (write into xr1 overlay)
    {
        dim3 grid(OUTD / 64, (N + 63) / 64);
        sgemm_kernel<<<grid, 256>>>(p_h, W2l, p_xl2, N, OUTD, HID);
        sgemm_kernel<<<grid, 256>>>(p_h, W2r, p_xr2, N, OUTD, HID);
    }

    // Layer 2 edge + softmax + aggregate + bias + LN -> out
    gat2_kernel<<<(N + 3) / 4, 128>>>(att2, b2, ln2g, ln2b, out, N);
}

// round 4
// speedup vs baseline: 1.4775x; 1.4775x over previous
#include <cuda_runtime.h>
#include <cuda_bf16.h>
#include <math.h>
#include <stdint.h>

#define NMAX 50000
#define EMAX 800000
#define ETOTAL (EMAX + NMAX)
#define IN_DIM 256
#define HID 64
#define L1C 256
#define OUTD 64

// ---------------- scratch (device globals; allocation-free) ----------------
__device__ float g_xl1[(size_t)NMAX * L1C];   // layer1 xl (51.2 MB)
__device__ float g_xr1[(size_t)NMAX * L1C];   // layer1 xr; reused for layer2 xl2/xr2
__device__ float g_h[(size_t)NMAX * HID];     // hidden after LN+ReLU
__device__ __nv_bfloat16 g_ahi[(size_t)NMAX * 256];  // A hi split (x, then h)
__device__ __nv_bfloat16 g_alo[(size_t)NMAX * 256];  // A lo split
__device__ __nv_bfloat16 g_bhi[512 * 256];           // packed W transposed [Ntot][K]
__device__ __nv_bfloat16 g_blo[512 * 256];
__device__ int   g_deg[NMAX + 1];
__device__ int   g_off[NMAX + 1];
__device__ int   g_cur[NMAX];
__device__ int   g_src[ETOTAL];

// ---------------- CSR build ----------------
__global__ void zero_deg_kernel(int n) {
    int i = blockIdx.x * blockDim.x + threadIdx.x;
    if (i <= n) g_deg[i] = 0;
}

__global__ void hist_kernel(const int* __restrict__ ei, int E, int n) {
    int e = blockIdx.x * blockDim.x + threadIdx.x;
    int tot = E + n;
    if (e < tot) {
        int d = (e < E) ? ei[E + e] : (e - E);
        if (d < 0) d = 0;
        if (d >= n) d = n - 1;
        atomicAdd(&g_deg[d], 1);
    }
}

__global__ void scan_kernel(int n) {
    __shared__ int partial[1024];
    int tid = threadIdx.x;
    int CH = (n + 1023) / 1024;
    int base = tid * CH;
    int s = 0;
    for (int i = 0; i < CH; i++) {
        int idx = base + i;
        if (idx < n) s += g_deg[idx];
    }
    partial[tid] = s;
    __syncthreads();
    for (int d = 1; d < 1024; d <<= 1) {
        int v = partial[tid];
        int add = (tid >= d) ? partial[tid - d] : 0;
        __syncthreads();
        partial[tid] = v + add;
        __syncthreads();
    }
    int run = (tid == 0) ? 0 : partial[tid - 1];
    for (int i = 0; i < CH; i++) {
        int idx = base + i;
        if (idx < n) {
            g_off[idx] = run;
            g_cur[idx] = run;
            run += g_deg[idx];
        }
    }
    if (tid == 0) g_off[n] = partial[1023];
}

__global__ void scatter_kernel(const int* __restrict__ ei, int E, int n) {
    int e = blockIdx.x * blockDim.x + threadIdx.x;
    int tot = E + n;
    if (e < tot) {
        int s, d;
        if (e < E) { s = ei[e]; d = ei[E + e]; }
        else       { s = d = e - E; }
        if (s < 0) s = 0; if (s >= n) s = n - 1;
        if (d < 0) d = 0; if (d >= n) d = n - 1;
        int pos = atomicAdd(&g_cur[d], 1);
        if (pos >= 0 && pos < ETOTAL) g_src[pos] = s;
    }
}

// ---------------- fp32 -> (hi, lo) bf16 split ----------------
__global__ void conv_split_kernel(const float* __restrict__ in,
                                  __nv_bfloat16* __restrict__ hi,
                                  __nv_bfloat16* __restrict__ lo, int n4) {
    int i = blockIdx.x * blockDim.x + threadIdx.x;
    if (i < n4) {
        float4 v = ((const float4*)in)[i];
        __nv_bfloat16 h0 = __float2bfloat16(v.x);
        __nv_bfloat16 h1 = __float2bfloat16(v.y);
        __nv_bfloat16 h2 = __float2bfloat16(v.z);
        __nv_bfloat16 h3 = __float2bfloat16(v.w);
        __nv_bfloat162 hh0{h0, h1}, hh1{h2, h3};
        ((__nv_bfloat162*)hi)[2 * i] = hh0;
        ((__nv_bfloat162*)hi)[2 * i + 1] = hh1;
        __nv_bfloat162 ll0{__float2bfloat16(v.x - __bfloat162float(h0)),
                           __float2bfloat16(v.y - __bfloat162float(h1))};
        __nv_bfloat162 ll1{__float2bfloat16(v.z - __bfloat162float(h2)),
                           __float2bfloat16(v.w - __bfloat162float(h3))};
        ((__nv_bfloat162*)lo)[2 * i] = ll0;
        ((__nv_bfloat162*)lo)[2 * i + 1] = ll1;
    }
}

// ---------------- pack Wl|Wr -> Bt[n][k] (transposed), hi/lo split ----------
__global__ void pack_bt_kernel(const float* __restrict__ Wl, const float* __restrict__ Wr,
                               __nv_bfloat16* __restrict__ bhi, __nv_bfloat16* __restrict__ blo,
                               int K, int Nhalf) {
    int idx = blockIdx.x * blockDim.x + threadIdx.x;
    int tot = 2 * Nhalf * K;
    if (idx < tot) {
        int n = idx / K, k = idx % K;
        float v = (n < Nhalf) ? Wl[(size_t)k * Nhalf + n] : Wr[(size_t)k * Nhalf + (n - Nhalf)];
        __nv_bfloat16 h = __float2bfloat16(v);
        bhi[idx] = h;
        blo[idx] = __float2bfloat16(v - __bfloat162float(h));
    }
}

// ---------------- tensor-core GEMM with 3-term bf16 split ----------------
// C[M, Ntot] = A[M, K] * Bt^T, A row-major bf16 hi/lo, Bt n-major [Ntot][K].
// Block tile 128x128, 8 warps (warp tile 64x32), K chunk 16.
__device__ __forceinline__ void mma_bf16(float d[4], const uint32_t a[4], const uint32_t b[2]) {
    asm volatile(
        "mma.sync.aligned.m16n8k16.row.col.f32.bf16.bf16.f32 "
        "{%0,%1,%2,%3}, {%4,%5,%6,%7}, {%8,%9}, {%0,%1,%2,%3};\n"
        : "+f"(d[0]), "+f"(d[1]), "+f"(d[2]), "+f"(d[3])
        : "r"(a[0]), "r"(a[1]), "r"(a[2]), "r"(a[3]), "r"(b[0]), "r"(b[1]));
}

template <int KCHUNKS>
__global__ __launch_bounds__(256, 2)
void mma_gemm_kernel(const __nv_bfloat16* __restrict__ Ahi, const __nv_bfloat16* __restrict__ Alo,
                     const __nv_bfloat16* __restrict__ Bhi, const __nv_bfloat16* __restrict__ Blo,
                     float* __restrict__ C0, float* __restrict__ C1,
                     int M, int ncut, int ld) {
    constexpr int K = KCHUNKS * 16;
    __shared__ __nv_bfloat16 As_hi[128][24];
    __shared__ __nv_bfloat16 As_lo[128][24];
    __shared__ __nv_bfloat16 Bs_hi[128][24];
    __shared__ __nv_bfloat16 Bs_lo[128][24];

    int t = threadIdx.x;
    int lane = t & 31, wid = t >> 5;
    int wm = wid & 1, wn = wid >> 1;          // 2 x 4 warp grid
    int group = lane >> 2, tig = lane & 3;
    int m0 = blockIdx.y * 128, n0 = blockIdx.x * 128;

    float acc[4][4][4];
#pragma unroll
    for (int i = 0; i < 4; i++)
#pragma unroll
        for (int j = 0; j < 4; j++)
#pragma unroll
            for (int q = 0; q < 4; q++) acc[i][j][q] = 0.f;

    int lrow = t >> 1, lkq = (t & 1) * 8;
    const uint4 z4 = make_uint4(0, 0, 0, 0);

    for (int c = 0; c < KCHUNKS; c++) {
        __syncthreads();
        int grow = m0 + lrow;
        uint4 va_hi = z4, va_lo = z4;
        if (grow < M) {
            va_hi = *(const uint4*)&Ahi[(size_t)grow * K + c * 16 + lkq];
            va_lo = *(const uint4*)&Alo[(size_t)grow * K + c * 16 + lkq];
        }
        *(uint4*)&As_hi[lrow][lkq] = va_hi;
        *(uint4*)&As_lo[lrow][lkq] = va_lo;
        uint4 vb_hi = *(const uint4*)&Bhi[(size_t)(n0 + lrow) * K + c * 16 + lkq];
        uint4 vb_lo = *(const uint4*)&Blo[(size_t)(n0 + lrow) * K + c * 16 + lkq];
        *(uint4*)&Bs_hi[lrow][lkq] = vb_hi;
        *(uint4*)&Bs_lo[lrow][lkq] = vb_lo;
        __syncthreads();

        uint32_t a_hi[4][4], a_lo[4][4];
#pragma unroll
        for (int mf = 0; mf < 4; mf++) {
            int r0 = wm * 64 + mf * 16 + group;
            a_hi[mf][0] = *(const uint32_t*)&As_hi[r0][tig * 2];
            a_hi[mf][1] = *(const uint32_t*)&As_hi[r0 + 8][tig * 2];
            a_hi[mf][2] = *(const uint32_t*)&As_hi[r0][tig * 2 + 8];
            a_hi[mf][3] = *(const uint32_t*)&As_hi[r0 + 8][tig * 2 + 8];
            a_lo[mf][0] = *(const uint32_t*)&As_lo[r0][tig * 2];
            a_lo[mf][1] = *(const uint32_t*)&As_lo[r0 + 8][tig * 2];
            a_lo[mf][2] = *(const uint32_t*)&As_lo[r0][tig * 2 + 8];
            a_lo[mf][3] = *(const uint32_t*)&As_lo[r0 + 8][tig * 2 + 8];
        }
#pragma unroll
        for (int nf = 0; nf < 4; nf++) {
            int c0 = wn * 32 + nf * 8 + group;
            uint32_t b_hi[2], b_lo[2];
            b_hi[0] = *(const uint32_t*)&Bs_hi[c0][tig * 2];
            b_hi[1] = *(const uint32_t*)&Bs_hi[c0][tig * 2 + 8];
            b_lo[0] = *(const uint32_t*)&Bs_lo[c0][tig * 2];
            b_lo[1] = *(const uint32_t*)&Bs_lo[c0][tig * 2 + 8];
#pragma unroll
            for (int mf = 0; mf < 4; mf++) {
                mma_bf16(acc[mf][nf], a_hi[mf], b_hi);
                mma_bf16(acc[mf][nf], a_hi[mf], b_lo);
                mma_bf16(acc[mf][nf], a_lo[mf], b_hi);
            }
        }
    }

    // epilogue
#pragma unroll
    for (int mf = 0; mf < 4; mf++) {
        int r = m0 + wm * 64 + mf * 16 + group;
#pragma unroll
        for (int nf = 0; nf < 4; nf++) {
            int cc = n0 + wn * 32 + nf * 8 + tig * 2;
            float* dst = C0;
            int ccol = cc;
            if (cc >= ncut) { dst = C1; ccol = cc - ncut; }
            if (r < M)
                *(float2*)&dst[(size_t)r * ld + ccol] = make_float2(acc[mf][nf][0], acc[mf][nf][1]);
            if (r + 8 < M)
                *(float2*)&dst[(size_t)(r + 8) * ld + ccol] = make_float2(acc[mf][nf][2], acc[mf][nf][3]);
        }
    }
}

// ---------------- Layer 1 GAT: warp h = head h, lane handles 2 channels ----
__global__ void gat1_kernel(const float* __restrict__ att1, const float* __restrict__ b1,
                            const float* __restrict__ lng, const float* __restrict__ lnb,
                            int Nn) {
    int i = blockIdx.x;
    int t = threadIdx.x;          // 0..127
    int h = t >> 5;               // warp = head 0..3
    int l = t & 31;
    __shared__ float sout[256];
    __shared__ float red[4];
    __shared__ float red2[4];

    float2 xr = ((const float2*)(g_xr1 + (size_t)i * L1C + h * 64))[l];
    float2 at = ((const float2*)att1)[h * 32 + l];
    float acc0 = 0.f, acc1 = 0.f, den = 0.f;
    int e0 = g_off[i], e1 = g_off[i + 1];
    for (int e = e0; e < e1; e++) {
        int j = g_src[e];
        float2 xl = ((const float2*)(g_xl1 + (size_t)j * L1C + h * 64))[l];
        float s0 = xl.x + xr.x; s0 = s0 > 0.f ? s0 : 0.2f * s0;
        float s1 = xl.y + xr.y; s1 = s1 > 0.f ? s1 : 0.2f * s1;
        float term = s0 * at.x + s1 * at.y;
#pragma unroll
        for (int o = 16; o; o >>= 1) term += __shfl_xor_sync(0xffffffffu, term, o);
        float a = expf(term);
        acc0 += a * xl.x; acc1 += a * xl.y; den += a;
    }
    float inv = 1.f / (den + 1e-16f);
    sout[h * 64 + 2 * l]     = acc0 * inv;
    sout[h * 64 + 2 * l + 1] = acc1 * inv;
    __syncthreads();

    float val = 0.f;
    if (t < 64)
        val = 0.25f * (sout[t] + sout[t + 64] + sout[t + 128] + sout[t + 192]) + b1[t];

    float v = (t < 64) ? val : 0.f;
#pragma unroll
    for (int o = 16; o; o >>= 1) v += __shfl_xor_sync(0xffffffffu, v, o);
    if (l == 0) red[h] = v;
    __syncthreads();
    float mu = (red[0] + red[1] + red[2] + red[3]) * (1.f / 64.f);
    float dd = (t < 64) ? (val - mu) : 0.f;
    float v2 = dd * dd;
#pragma unroll
    for (int o = 16; o; o >>= 1) v2 += __shfl_xor_sync(0xffffffffu, v2, o);
    if (l == 0) red2[h] = v2;
    __syncthreads();
    float var = (red2[0] + red2[1] + red2[2] + red2[3]) * (1.f / 64.f);
    if (t < 64) {
        float y = dd * rsqrtf(var + 1e-5f) * lng[t] + lnb[t];
        g_h[(size_t)i * HID + t] = fmaxf(y, 0.f);
    }
}

// ---------------- Layer 2 GAT: warp per node, 1 head, LN fused, -> d_out ----
__global__ void gat2_kernel(const float* __restrict__ att2, const float* __restrict__ b2,
                            const float* __restrict__ lng, const float* __restrict__ lnb,
                            float* __restrict__ out, int Nn) {
    int w = threadIdx.x >> 5, l = threadIdx.x & 31;
    int i = blockIdx.x * 4 + w;
    if (i >= Nn) return;
    const float* xl2 = g_xr1;                               // overlay
    const float* xr2 = g_xr1 + (size_t)NMAX * OUTD;         // overlay

    float2 xr = ((const float2*)(xr2 + (size_t)i * OUTD))[l];
    float2 at = ((const float2*)att2)[l];
    float acc0 = 0.f, acc1 = 0.f, den = 0.f;
    int e0 = g_off[i], e1 = g_off[i + 1];
    for (int e = e0; e < e1; e++) {
        int j = g_src[e];
        float2 xl = ((const float2*)(xl2 + (size_t)j * OUTD))[l];
        float s0 = xl.x + xr.x; s0 = s0 > 0.f ? s0 : 0.2f * s0;
        float s1 = xl.y + xr.y; s1 = s1 > 0.f ? s1 : 0.2f * s1;
        float term = s0 * at.x + s1 * at.y;
#pragma unroll
        for (int o = 16; o; o >>= 1) term += __shfl_xor_sync(0xffffffffu, term, o);
        float a = expf(term);
        acc0 += a * xl.x; acc1 += a * xl.y; den += a;
    }
    float inv = 1.f / (den + 1e-16f);
    float2 bb = ((const float2*)b2)[l];
    float v0 = acc0 * inv + bb.x;
    float v1 = acc1 * inv + bb.y;

    float s = v0 + v1;
#pragma unroll
    for (int o = 16; o; o >>= 1) s += __shfl_xor_sync(0xffffffffu, s, o);
    float mu = s * (1.f / 64.f);
    float d0 = v0 - mu, d1 = v1 - mu;
    float q = d0 * d0 + d1 * d1;
#pragma unroll
    for (int o = 16; o; o >>= 1) q += __shfl_xor_sync(0xffffffffu, q, o);
    float var = q * (1.f / 64.f);
    float r = rsqrtf(var + 1e-5f);
    float2 gg = ((const float2*)lng)[l];
    float2 bn = ((const float2*)lnb)[l];
    float2 o2;
    o2.x = d0 * r * gg.x + bn.x;
    o2.y = d1 * r * gg.y + bn.y;
    ((float2*)(out + (size_t)i * OUTD))[l] = o2;
}

// ---------------- launch ----------------
extern "C" void kernel_launch(void* const* d_in, const int* in_sizes, int n_in,
                              void* d_out, int out_size) {
    const float* x    = (const float*)d_in[0];
    const int*   ei   = (const int*)d_in[1];
    const float* W1l  = (const float*)d_in[2];
    const float* W1r  = (const float*)d_in[3];
    const float* att1 = (const float*)d_in[4];
    const float* b1   = (const float*)d_in[5];
    const float* ln1g = (const float*)d_in[6];
    const float* ln1b = (const float*)d_in[7];
    const float* W2l  = (const float*)d_in[8];
    const float* W2r  = (const float*)d_in[9];
    const float* att2 = (const float*)d_in[10];
    const float* b2   = (const float*)d_in[11];
    const float* ln2g = (const float*)d_in[12];
    const float* ln2b = (const float*)d_in[13];
    float* out = (float*)d_out;

    int N = in_sizes[0] / IN_DIM;
    int E = in_sizes[1] / 2;
    if (N > NMAX) N = NMAX;
    if (E > EMAX) E = EMAX;
    int ETOT_RT = E + N;

    float *p_xl1, *p_xr1, *p_h;
    __nv_bfloat16 *p_ahi, *p_alo, *p_bhi, *p_blo;
    cudaGetSymbolAddress((void**)&p_xl1, g_xl1);
    cudaGetSymbolAddress((void**)&p_xr1, g_xr1);
    cudaGetSymbolAddress((void**)&p_h,   g_h);
    cudaGetSymbolAddress((void**)&p_ahi, g_ahi);
    cudaGetSymbolAddress((void**)&p_alo, g_alo);
    cudaGetSymbolAddress((void**)&p_bhi, g_bhi);
    cudaGetSymbolAddress((void**)&p_blo, g_blo);
    float* p_xl2 = p_xr1;                              // overlay for layer 2
    float* p_xr2 = p_xr1 + (size_t)NMAX * OUTD;

    // CSR build
    zero_deg_kernel<<<(N + 256) / 256, 256>>>(N);
    hist_kernel<<<(ETOT_RT + 255) / 256, 256>>>(ei, E, N);
    scan_kernel<<<1, 1024>>>(N);
    scatter_kernel<<<(ETOT_RT + 255) / 256, 256>>>(ei, E, N);

    // Layer 1: split x, pack W, fused tensor-core GEMM -> xl1 | xr1
    {
        int n4 = N * IN_DIM / 4;
        conv_split_kernel<<<(n4 + 255) / 256, 256>>>(x, p_ahi, p_alo, n4);
        pack_bt_kernel<<<(512 * 256 + 255) / 256, 256>>>(W1l, W1r, p_bhi, p_blo, 256, 256);
        dim3 grid(512 / 128, (N + 127) / 128);
        mma_gemm_kernel<16><<<grid, 256>>>(p_ahi, p_alo, p_bhi, p_blo,
                                           p_xl1, p_xr1, N, 256, 256);
    }

    // Layer 1 edge + softmax + aggregate + heads-mean + bias + LN + ReLU
    gat1_kernel<<<N, 128>>>(att1, b1, ln1g, ln1b, N);

    // Layer 2: split h, pack W2, fused GEMM -> xl2 | xr2 (overlay)
    {
        int n4 = N * HID / 4;
        conv_split_kernel<<<(n4 + 255) / 256, 256>>>(p_h, p_ahi, p_alo, n4);
        pack_bt_kernel<<<(128 * 64 + 255) / 256, 256>>>(W2l, W2r, p_bhi, p_blo, 64, 64);
        dim3 grid(128 / 128, (N + 127) / 128);
        mma_gemm_kernel<4><<<grid, 256>>>(p_ahi, p_alo, p_bhi, p_blo,
                                          p_xl2, p_xr2, N, 64, 64);
    }

    // Layer 2 edge + softmax + aggregate + bias + LN -> out
    gat2_kernel<<<(N + 3) / 4, 128>>>(att2, b2, ln2g, ln2b, out, N);
}

// round 5
// speedup vs baseline: 1.5674x; 1.0608x over previous
#include <cuda_runtime.h>
#include <cuda_bf16.h>
#include <math.h>
#include <stdint.h>

#define NMAX 50000
#define EMAX 800000
#define ETOTAL (EMAX + NMAX)
#define IN_DIM 256
#define HID 64
#define L1C 256
#define OUTD 64

// ---------------- scratch (device globals; allocation-free) ----------------
__device__ float g_xl1[(size_t)NMAX * L1C];
__device__ float g_xr1[(size_t)NMAX * L1C];   // reused for layer2 xl2/xr2
__device__ float g_h[(size_t)NMAX * HID];
__device__ __nv_bfloat16 g_ahi[(size_t)NMAX * 256];
__device__ __nv_bfloat16 g_alo[(size_t)NMAX * 256];
__device__ __nv_bfloat16 g_bhi[512 * 256];
__device__ __nv_bfloat16 g_blo[512 * 256];
__device__ int   g_deg[NMAX + 1];
__device__ int   g_off[NMAX + 1];
__device__ int   g_cur[NMAX];
__device__ int   g_src[ETOTAL];

// ---------------- CSR build ----------------
__global__ void zero_deg_kernel(int n) {
    int i = blockIdx.x * blockDim.x + threadIdx.x;
    if (i <= n) g_deg[i] = 0;
}

__global__ void hist_kernel(const int* __restrict__ ei, int E, int n) {
    int e = blockIdx.x * blockDim.x + threadIdx.x;
    int tot = E + n;
    if (e < tot) {
        int d = (e < E) ? ei[E + e] : (e - E);
        if (d < 0) d = 0;
        if (d >= n) d = n - 1;
        atomicAdd(&g_deg[d], 1);
    }
}

__global__ void scan_kernel(int n) {
    __shared__ int partial[1024];
    int tid = threadIdx.x;
    int CH = (n + 1023) / 1024;
    int base = tid * CH;
    int s = 0;
    for (int i = 0; i < CH; i++) {
        int idx = base + i;
        if (idx < n) s += g_deg[idx];
    }
    partial[tid] = s;
    __syncthreads();
    for (int d = 1; d < 1024; d <<= 1) {
        int v = partial[tid];
        int add = (tid >= d) ? partial[tid - d] : 0;
        __syncthreads();
        partial[tid] = v + add;
        __syncthreads();
    }
    int run = (tid == 0) ? 0 : partial[tid - 1];
    for (int i = 0; i < CH; i++) {
        int idx = base + i;
        if (idx < n) {
            g_off[idx] = run;
            g_cur[idx] = run;
            run += g_deg[idx];
        }
    }
    if (tid == 0) g_off[n] = partial[1023];
}

__global__ void scatter_kernel(const int* __restrict__ ei, int E, int n) {
    int e = blockIdx.x * blockDim.x + threadIdx.x;
    int tot = E + n;
    if (e < tot) {
        int s, d;
        if (e < E) { s = ei[e]; d = ei[E + e]; }
        else       { s = d = e - E; }
        if (s < 0) s = 0; if (s >= n) s = n - 1;
        if (d < 0) d = 0; if (d >= n) d = n - 1;
        int pos = atomicAdd(&g_cur[d], 1);
        if (pos >= 0 && pos < ETOTAL) g_src[pos] = s;
    }
}

// ---------------- fp32 -> (hi, lo) bf16 split ----------------
__global__ void conv_split_kernel(const float* __restrict__ in,
                                  __nv_bfloat16* __restrict__ hi,
                                  __nv_bfloat16* __restrict__ lo, int n4) {
    int i = blockIdx.x * blockDim.x + threadIdx.x;
    if (i < n4) {
        float4 v = ((const float4*)in)[i];
        __nv_bfloat16 h0 = __float2bfloat16(v.x);
        __nv_bfloat16 h1 = __float2bfloat16(v.y);
        __nv_bfloat16 h2 = __float2bfloat16(v.z);
        __nv_bfloat16 h3 = __float2bfloat16(v.w);
        __nv_bfloat162 hh0{h0, h1}, hh1{h2, h3};
        ((__nv_bfloat162*)hi)[2 * i] = hh0;
        ((__nv_bfloat162*)hi)[2 * i + 1] = hh1;
        __nv_bfloat162 ll0{__float2bfloat16(v.x - __bfloat162float(h0)),
                           __float2bfloat16(v.y - __bfloat162float(h1))};
        __nv_bfloat162 ll1{__float2bfloat16(v.z - __bfloat162float(h2)),
                           __float2bfloat16(v.w - __bfloat162float(h3))};
        ((__nv_bfloat162*)lo)[2 * i] = ll0;
        ((__nv_bfloat162*)lo)[2 * i + 1] = ll1;
    }
}

// ---------------- pack Wl|Wr -> Bt[n][k] (transposed), hi/lo split ----------
__global__ void pack_bt_kernel(const float* __restrict__ Wl, const float* __restrict__ Wr,
                               __nv_bfloat16* __restrict__ bhi, __nv_bfloat16* __restrict__ blo,
                               int K, int Nhalf) {
    int idx = blockIdx.x * blockDim.x + threadIdx.x;
    int tot = 2 * Nhalf * K;
    if (idx < tot) {
        int n = idx / K, k = idx % K;
        float v = (n < Nhalf) ? Wl[(size_t)k * Nhalf + n] : Wr[(size_t)k * Nhalf + (n - Nhalf)];
        __nv_bfloat16 h = __float2bfloat16(v);
        bhi[idx] = h;
        blo[idx] = __float2bfloat16(v - __bfloat162float(h));
    }
}

// ---------------- async copy helpers ----------------
__device__ __forceinline__ void cp16(void* sdst, const void* gsrc, int src_bytes) {
    uint32_t s = (uint32_t)__cvta_generic_to_shared(sdst);
    asm volatile("cp.async.cg.shared.global [%0], [%1], 16, %2;\n"
                 :: "r"(s), "l"(gsrc), "r"(src_bytes));
}
__device__ __forceinline__ void cp_commit() { asm volatile("cp.async.commit_group;\n"); }
__device__ __forceinline__ void cp_wait1() { asm volatile("cp.async.wait_group 1;\n"); }
__device__ __forceinline__ void cp_wait0() { asm volatile("cp.async.wait_group 0;\n"); }

// ---------------- tensor-core GEMM, 3-term bf16 split, cp.async 2-stage ----
__device__ __forceinline__ void mma_bf16(float d[4], const uint32_t a[4], const uint32_t b[2]) {
    asm volatile(
        "mma.sync.aligned.m16n8k16.row.col.f32.bf16.bf16.f32 "
        "{%0,%1,%2,%3}, {%4,%5,%6,%7}, {%8,%9}, {%0,%1,%2,%3};\n"
        : "+f"(d[0]), "+f"(d[1]), "+f"(d[2]), "+f"(d[3])
        : "r"(a[0]), "r"(a[1]), "r"(a[2]), "r"(a[3]), "r"(b[0]), "r"(b[1]));
}

template <int KCHUNKS>
__global__ __launch_bounds__(256, 2)
void mma_gemm_kernel(const __nv_bfloat16* __restrict__ Ahi, const __nv_bfloat16* __restrict__ Alo,
                     const __nv_bfloat16* __restrict__ Bhi, const __nv_bfloat16* __restrict__ Blo,
                     float* __restrict__ C0, float* __restrict__ C1,
                     int M, int ncut, int ld) {
    constexpr int K = KCHUNKS * 16;
    __shared__ __nv_bfloat16 As_hi[2][128][24];
    __shared__ __nv_bfloat16 As_lo[2][128][24];
    __shared__ __nv_bfloat16 Bs_hi[2][128][24];
    __shared__ __nv_bfloat16 Bs_lo[2][128][24];

    int t = threadIdx.x;
    int lane = t & 31, wid = t >> 5;
    int wm = wid & 1, wn = wid >> 1;          // 2 x 4 warp grid
    int group = lane >> 2, tig = lane & 3;
    int m0 = blockIdx.y * 128, n0 = blockIdx.x * 128;

    float acc[4][4][4];
#pragma unroll
    for (int i = 0; i < 4; i++)
#pragma unroll
        for (int j = 0; j < 4; j++)
#pragma unroll
            for (int q = 0; q < 4; q++) acc[i][j][q] = 0.f;

    int lrow = t >> 1, lkq = (t & 1) * 8;
    int grow = m0 + lrow;
    int abytes = (grow < M) ? 16 : 0;
    const __nv_bfloat16* pAhi = Ahi + (size_t)(grow < M ? grow : 0) * K + lkq;
    const __nv_bfloat16* pAlo = Alo + (size_t)(grow < M ? grow : 0) * K + lkq;
    const __nv_bfloat16* pBhi = Bhi + (size_t)(n0 + lrow) * K + lkq;
    const __nv_bfloat16* pBlo = Blo + (size_t)(n0 + lrow) * K + lkq;

    // prologue: stage 0
    cp16(&As_hi[0][lrow][lkq], pAhi, abytes);
    cp16(&As_lo[0][lrow][lkq], pAlo, abytes);
    cp16(&Bs_hi[0][lrow][lkq], pBhi, 16);
    cp16(&Bs_lo[0][lrow][lkq], pBlo, 16);
    cp_commit();

#pragma unroll
    for (int c = 0; c < KCHUNKS; c++) {
        if (c + 1 < KCHUNKS) {
            int st = (c + 1) & 1;
            int ko = (c + 1) * 16;
            cp16(&As_hi[st][lrow][lkq], pAhi + ko, abytes);
            cp16(&As_lo[st][lrow][lkq], pAlo + ko, abytes);
            cp16(&Bs_hi[st][lrow][lkq], pBhi + ko, 16);
            cp16(&Bs_lo[st][lrow][lkq], pBlo + ko, 16);
            cp_commit();
            cp_wait1();
        } else {
            cp_wait0();
        }
        __syncthreads();

        int st = c & 1;
        uint32_t a_hi[4][4], a_lo[4][4];
#pragma unroll
        for (int mf = 0; mf < 4; mf++) {
            int r0 = wm * 64 + mf * 16 + group;
            a_hi[mf][0] = *(const uint32_t*)&As_hi[st][r0][tig * 2];
            a_hi[mf][1] = *(const uint32_t*)&As_hi[st][r0 + 8][tig * 2];
            a_hi[mf][2] = *(const uint32_t*)&As_hi[st][r0][tig * 2 + 8];
            a_hi[mf][3] = *(const uint32_t*)&As_hi[st][r0 + 8][tig * 2 + 8];
            a_lo[mf][0] = *(const uint32_t*)&As_lo[st][r0][tig * 2];
            a_lo[mf][1] = *(const uint32_t*)&As_lo[st][r0 + 8][tig * 2];
            a_lo[mf][2] = *(const uint32_t*)&As_lo[st][r0][tig * 2 + 8];
            a_lo[mf][3] = *(const uint32_t*)&As_lo[st][r0 + 8][tig * 2 + 8];
        }
#pragma unroll
        for (int nf = 0; nf < 4; nf++) {
            int c0 = wn * 32 + nf * 8 + group;
            uint32_t b_hi[2], b_lo[2];
            b_hi[0] = *(const uint32_t*)&Bs_hi[st][c0][tig * 2];
            b_hi[1] = *(const uint32_t*)&Bs_hi[st][c0][tig * 2 + 8];
            b_lo[0] = *(const uint32_t*)&Bs_lo[st][c0][tig * 2];
            b_lo[1] = *(const uint32_t*)&Bs_lo[st][c0][tig * 2 + 8];
#pragma unroll
            for (int mf = 0; mf < 4; mf++) {
                mma_bf16(acc[mf][nf], a_hi[mf], b_hi);
                mma_bf16(acc[mf][nf], a_hi[mf], b_lo);
                mma_bf16(acc[mf][nf], a_lo[mf], b_hi);
            }
        }
        __syncthreads();
    }

    // epilogue
#pragma unroll
    for (int mf = 0; mf < 4; mf++) {
        int r = m0 + wm * 64 + mf * 16 + group;
#pragma unroll
        for (int nf = 0; nf < 4; nf++) {
            int cc = n0 + wn * 32 + nf * 8 + tig * 2;
            float* dst = C0;
            int ccol = cc;
            if (cc >= ncut) { dst = C1; ccol = cc - ncut; }
            if (r < M)
                *(float2*)&dst[(size_t)r * ld + ccol] = make_float2(acc[mf][nf][0], acc[mf][nf][1]);
            if (r + 8 < M)
                *(float2*)&dst[(size_t)(r + 8) * ld + ccol] = make_float2(acc[mf][nf][2], acc[mf][nf][3]);
        }
    }
}

// ---------------- Layer 1 GAT: warp h = head h, 2-edge unrolled ----------
__global__ void gat1_kernel(const float* __restrict__ att1, const float* __restrict__ b1,
                            const float* __restrict__ lng, const float* __restrict__ lnb,
                            int Nn) {
    int i = blockIdx.x;
    int t = threadIdx.x;          // 0..127
    int h = t >> 5;               // warp = head 0..3
    int l = t & 31;
    __shared__ float sout[256];
    __shared__ float red[4];
    __shared__ float red2[4];

    float2 xr = ((const float2*)(g_xr1 + (size_t)i * L1C + h * 64))[l];
    float2 at = ((const float2*)att1)[h * 32 + l];
    float acc0 = 0.f, acc1 = 0.f, den = 0.f;
    int e0 = g_off[i], e1 = g_off[i + 1];
    int e = e0;
    for (; e + 1 < e1; e += 2) {
        int j0 = g_src[e], j1 = g_src[e + 1];
        float2 xa = ((const float2*)(g_xl1 + (size_t)j0 * L1C + h * 64))[l];
        float2 xb = ((const float2*)(g_xl1 + (size_t)j1 * L1C + h * 64))[l];
        float sa0 = xa.x + xr.x; sa0 = sa0 > 0.f ? sa0 : 0.2f * sa0;
        float sa1 = xa.y + xr.y; sa1 = sa1 > 0.f ? sa1 : 0.2f * sa1;
        float sb0 = xb.x + xr.x; sb0 = sb0 > 0.f ? sb0 : 0.2f * sb0;
        float sb1 = xb.y + xr.y; sb1 = sb1 > 0.f ? sb1 : 0.2f * sb1;
        float ta = sa0 * at.x + sa1 * at.y;
        float tb = sb0 * at.x + sb1 * at.y;
#pragma unroll
        for (int o = 16; o; o >>= 1) {
            ta += __shfl_xor_sync(0xffffffffu, ta, o);
            tb += __shfl_xor_sync(0xffffffffu, tb, o);
        }
        float aa = __expf(ta), ab = __expf(tb);
        acc0 += aa * xa.x + ab * xb.x;
        acc1 += aa * xa.y + ab * xb.y;
        den += aa + ab;
    }
    if (e < e1) {
        int j = g_src[e];
        float2 xl = ((const float2*)(g_xl1 + (size_t)j * L1C + h * 64))[l];
        float s0 = xl.x + xr.x; s0 = s0 > 0.f ? s0 : 0.2f * s0;
        float s1 = xl.y + xr.y; s1 = s1 > 0.f ? s1 : 0.2f * s1;
        float term = s0 * at.x + s1 * at.y;
#pragma unroll
        for (int o = 16; o; o >>= 1) term += __shfl_xor_sync(0xffffffffu, term, o);
        float a = __expf(term);
        acc0 += a * xl.x; acc1 += a * xl.y; den += a;
    }
    float inv = 1.f / (den + 1e-16f);
    sout[h * 64 + 2 * l]     = acc0 * inv;
    sout[h * 64 + 2 * l + 1] = acc1 * inv;
    __syncthreads();

    float val = 0.f;
    if (t < 64)
        val = 0.25f * (sout[t] + sout[t + 64] + sout[t + 128] + sout[t + 192]) + b1[t];

    float v = (t < 64) ? val : 0.f;
#pragma unroll
    for (int o = 16; o; o >>= 1) v += __shfl_xor_sync(0xffffffffu, v, o);
    if (l == 0) red[h] = v;
    __syncthreads();
    float mu = (red[0] + red[1] + red[2] + red[3]) * (1.f / 64.f);
    float dd = (t < 64) ? (val - mu) : 0.f;
    float v2 = dd * dd;
#pragma unroll
    for (int o = 16; o; o >>= 1) v2 += __shfl_xor_sync(0xffffffffu, v2, o);
    if (l == 0) red2[h] = v2;
    __syncthreads();
    float var = (red2[0] + red2[1] + red2[2] + red2[3]) * (1.f / 64.f);
    if (t < 64) {
        float y = dd * rsqrtf(var + 1e-5f) * lng[t] + lnb[t];
        g_h[(size_t)i * HID + t] = fmaxf(y, 0.f);
    }
}

// ---------------- Layer 2 GAT: warp per node, 2-edge unrolled ------------
__global__ void gat2_kernel(const float* __restrict__ att2, const float* __restrict__ b2,
                            const float* __restrict__ lng, const float* __restrict__ lnb,
                            float* __restrict__ out, int Nn) {
    int w = threadIdx.x >> 5, l = threadIdx.x & 31;
    int i = blockIdx.x * 4 + w;
    if (i >= Nn) return;
    const float* xl2 = g_xr1;                               // overlay
    const float* xr2 = g_xr1 + (size_t)NMAX * OUTD;         // overlay

    float2 xr = ((const float2*)(xr2 + (size_t)i * OUTD))[l];
    float2 at = ((const float2*)att2)[l];
    float acc0 = 0.f, acc1 = 0.f, den = 0.f;
    int e0 = g_off[i], e1 = g_off[i + 1];
    int e = e0;
    for (; e + 1 < e1; e += 2) {
        int j0 = g_src[e], j1 = g_src[e + 1];
        float2 xa = ((const float2*)(xl2 + (size_t)j0 * OUTD))[l];
        float2 xb = ((const float2*)(xl2 + (size_t)j1 * OUTD))[l];
        float sa0 = xa.x + xr.x; sa0 = sa0 > 0.f ? sa0 : 0.2f * sa0;
        float sa1 = xa.y + xr.y; sa1 = sa1 > 0.f ? sa1 : 0.2f * sa1;
        float sb0 = xb.x + xr.x; sb0 = sb0 > 0.f ? sb0 : 0.2f * sb0;
        float sb1 = xb.y + xr.y; sb1 = sb1 > 0.f ? sb1 : 0.2f * sb1;
        float ta = sa0 * at.x + sa1 * at.y;
        float tb = sb0 * at.x + sb1 * at.y;
#pragma unroll
        for (int o = 16; o; o >>= 1) {
            ta += __shfl_xor_sync(0xffffffffu, ta, o);
            tb += __shfl_xor_sync(0xffffffffu, tb, o);
        }
        float aa = __expf(ta), ab = __expf(tb);
        acc0 += aa * xa.x + ab * xb.x;
        acc1 += aa * xa.y + ab * xb.y;
        den += aa + ab;
    }
    if (e < e1) {
        int j = g_src[e];
        float2 xl = ((const float2*)(xl2 + (size_t)j * OUTD))[l];
        float s0 = xl.x + xr.x; s0 = s0 > 0.f ? s0 : 0.2f * s0;
        float s1 = xl.y + xr.y; s1 = s1 > 0.f ? s1 : 0.2f * s1;
        float term = s0 * at.x + s1 * at.y;
#pragma unroll
        for (int o = 16; o; o >>= 1) term += __shfl_xor_sync(0xffffffffu, term, o);
        float a = __expf(term);
        acc0 += a * xl.x; acc1 += a * xl.y; den += a;
    }
    float inv = 1.f / (den + 1e-16f);
    float2 bb = ((const float2*)b2)[l];
    float v0 = acc0 * inv + bb.x;
    float v1 = acc1 * inv + bb.y;

    float s = v0 + v1;
#pragma unroll
    for (int o = 16; o; o >>= 1) s += __shfl_xor_sync(0xffffffffu, s, o);
    float mu = s * (1.f / 64.f);
    float d0 = v0 - mu, d1 = v1 - mu;
    float q = d0 * d0 + d1 * d1;
#pragma unroll
    for (int o = 16; o; o >>= 1) q += __shfl_xor_sync(0xffffffffu, q, o);
    float var = q * (1.f / 64.f);
    float r = rsqrtf(var + 1e-5f);
    float2 gg = ((const float2*)lng)[l];
    float2 bn = ((const float2*)lnb)[l];
    float2 o2;
    o2.x = d0 * r * gg.x + bn.x;
    o2.y = d1 * r * gg.y + bn.y;
    ((float2*)(out + (size_t)i * OUTD))[l] = o2;
}

// ---------------- launch ----------------
extern "C" void kernel_launch(void* const* d_in, const int* in_sizes, int n_in,
                              void* d_out, int out_size) {
    const float* x    = (const float*)d_in[0];
    const int*   ei   = (const int*)d_in[1];
    const float* W1l  = (const float*)d_in[2];
    const float* W1r  = (const float*)d_in[3];
    const float* att1 = (const float*)d_in[4];
    const float* b1   = (const float*)d_in[5];
    const float* ln1g = (const float*)d_in[6];
    const float* ln1b = (const float*)d_in[7];
    const float* W2l  = (const float*)d_in[8];
    const float* W2r  = (const float*)d_in[9];
    const float* att2 = (const float*)d_in[10];
    const float* b2   = (const float*)d_in[11];
    const float* ln2g = (const float*)d_in[12];
    const float* ln2b = (const float*)d_in[13];
    float* out = (float*)d_out;

    int N = in_sizes[0] / IN_DIM;
    int E = in_sizes[1] / 2;
    if (N > NMAX) N = NMAX;
    if (E > EMAX) E = EMAX;
    int ETOT_RT = E + N;

    float *p_xl1, *p_xr1, *p_h;
    __nv_bfloat16 *p_ahi, *p_alo, *p_bhi, *p_blo;
    cudaGetSymbolAddress((void**)&p_xl1, g_xl1);
    cudaGetSymbolAddress((void**)&p_xr1, g_xr1);
    cudaGetSymbolAddress((void**)&p_h,   g_h);
    cudaGetSymbolAddress((void**)&p_ahi, g_ahi);
    cudaGetSymbolAddress((void**)&p_alo, g_alo);
    cudaGetSymbolAddress((void**)&p_bhi, g_bhi);
    cudaGetSymbolAddress((void**)&p_blo, g_blo);
    float* p_xl2 = p_xr1;                              // overlay for layer 2
    float* p_xr2 = p_xr1 + (size_t)NMAX * OUTD;

    // CSR build
    zero_deg_kernel<<<(N + 256) / 256, 256>>>(N);
    hist_kernel<<<(ETOT_RT + 255) / 256, 256>>>(ei, E, N);
    scan_kernel<<<1, 1024>>>(N);
    scatter_kernel<<<(ETOT_RT + 255) / 256, 256>>>(ei, E, N);

    // Layer 1: split x, pack W, fused tensor-core GEMM -> xl1 | xr1
    {
        int n4 = N * IN_DIM / 4;
        conv_split_kernel<<<(n4 + 255) / 256, 256>>>(x, p_ahi, p_alo, n4);
        pack_bt_kernel<<<(512 * 256 + 255) / 256, 256>>>(W1l, W1r, p_bhi, p_blo, 256, 256);
        dim3 grid(512 / 128, (N + 127) / 128);
        mma_gemm_kernel<16><<<grid, 256>>>(p_ahi, p_alo, p_bhi, p_blo,
                                           p_xl1, p_xr1, N, 256, 256);
    }

    // Layer 1 edge + softmax + aggregate + heads-mean + bias + LN + ReLU
    gat1_kernel<<<N, 128>>>(att1, b1, ln1g, ln1b, N);

    // Layer 2: split h, pack W2, fused GEMM -> xl2 | xr2 (overlay)
    {
        int n4 = N * HID / 4;
        conv_split_kernel<<<(n4 + 255) / 256, 256>>>(p_h, p_ahi, p_alo, n4);
        pack_bt_kernel<<<(128 * 64 + 255) / 256, 256>>>(W2l, W2r, p_bhi, p_blo, 64, 64);
        dim3 grid(128 / 128, (N + 127) / 128);
        mma_gemm_kernel<4><<<grid, 256>>>(p_ahi, p_alo, p_bhi, p_blo,
                                          p_xl2, p_xr2, N, 64, 64);
    }

    // Layer 2 edge + softmax + aggregate + bias + LN -> out
    gat2_kernel<<<(N + 3) / 4, 128>>>(att2, b2, ln2g, ln2b, out, N);
}

// round 6
// speedup vs baseline: 1.8730x; 1.1950x over previous
#include <cuda_runtime.h>
#include <cuda_bf16.h>
#include <math.h>
#include <stdint.h>

#define NMAX 50000
#define EMAX 800000
#define ETOTAL (EMAX + NMAX)
#define IN_DIM 256
#define HID 64
#define L1C 256
#define OUTD 64
#define SCAN_BLK 1024
#define NSCAN ((NMAX + SCAN_BLK - 1) / SCAN_BLK)

// ---------------- scratch (device globals; allocation-free) ----------------
__device__ float g_xl1[(size_t)NMAX * L1C];
__device__ float g_xr1[(size_t)NMAX * L1C];   // reused for layer2 xl2/xr2
__device__ float g_h[(size_t)NMAX * HID];
__device__ __nv_bfloat16 g_ahi[(size_t)NMAX * 256];
__device__ __nv_bfloat16 g_alo[(size_t)NMAX * 256];
__device__ __nv_bfloat16 g_bhi[512 * 256];
__device__ __nv_bfloat16 g_blo[512 * 256];
__device__ int   g_deg[NMAX + 1];
__device__ int   g_off[NMAX + 1];
__device__ int   g_cur[NMAX];
__device__ int   g_src[ETOTAL];
__device__ int   g_bsum[NSCAN + 1];

// ---------------- CSR build ----------------
__global__ void zero_deg_kernel(int n) {
    int i = blockIdx.x * blockDim.x + threadIdx.x;
    if (i <= n) g_deg[i] = 0;
}

__global__ void hist_kernel(const int* __restrict__ ei, int E, int n) {
    int e = blockIdx.x * blockDim.x + threadIdx.x;
    int tot = E + n;
    if (e < tot) {
        int d = (e < E) ? ei[E + e] : (e - E);
        if (d < 0) d = 0;
        if (d >= n) d = n - 1;
        atomicAdd(&g_deg[d], 1);
    }
}

// phase 1: per-block exclusive scan of deg -> off (local), block sums -> g_bsum
__global__ void scan1_kernel(int n) {
    __shared__ int sh[SCAN_BLK];
    int tid = threadIdx.x;
    int idx = blockIdx.x * SCAN_BLK + tid;
    int v = (idx < n) ? g_deg[idx] : 0;
    sh[tid] = v;
    __syncthreads();
    for (int d = 1; d < SCAN_BLK; d <<= 1) {
        int t = sh[tid];
        int add = (tid >= d) ? sh[tid - d] : 0;
        __syncthreads();
        sh[tid] = t + add;
        __syncthreads();
    }
    if (idx < n) g_off[idx] = sh[tid] - v;   // exclusive within block
    if (tid == SCAN_BLK - 1) g_bsum[blockIdx.x] = sh[tid];
}

// phase 2: serial scan of block sums (small)
__global__ void scan2_kernel(int nb, int n) {
    if (threadIdx.x == 0) {
        int run = 0;
        for (int b = 0; b < nb; b++) {
            int t = g_bsum[b];
            g_bsum[b] = run;
            run += t;
        }
        g_off[n] = run;
    }
}

// phase 3: add block offsets, init cursor
__global__ void scan3_kernel(int n) {
    int idx = blockIdx.x * SCAN_BLK + threadIdx.x;
    if (idx < n) {
        int o = g_off[idx] + g_bsum[blockIdx.x];
        g_off[idx] = o;
        g_cur[idx] = o;
    }
}

__global__ void scatter_kernel(const int* __restrict__ ei, int E, int n) {
    int e = blockIdx.x * blockDim.x + threadIdx.x;
    int tot = E + n;
    if (e < tot) {
        int s, d;
        if (e < E) { s = ei[e]; d = ei[E + e]; }
        else       { s = d = e - E; }
        if (s < 0) s = 0; if (s >= n) s = n - 1;
        if (d < 0) d = 0; if (d >= n) d = n - 1;
        int pos = atomicAdd(&g_cur[d], 1);
        if (pos >= 0 && pos < ETOTAL) g_src[pos] = s;
    }
}

// ---------------- fp32 -> (hi, lo) bf16 split ----------------
__global__ void conv_split_kernel(const float* __restrict__ in,
                                  __nv_bfloat16* __restrict__ hi,
                                  __nv_bfloat16* __restrict__ lo, int n4) {
    int i = blockIdx.x * blockDim.x + threadIdx.x;
    if (i < n4) {
        float4 v = ((const float4*)in)[i];
        __nv_bfloat16 h0 = __float2bfloat16(v.x);
        __nv_bfloat16 h1 = __float2bfloat16(v.y);
        __nv_bfloat16 h2 = __float2bfloat16(v.z);
        __nv_bfloat16 h3 = __float2bfloat16(v.w);
        __nv_bfloat162 hh0{h0, h1}, hh1{h2, h3};
        ((__nv_bfloat162*)hi)[2 * i] = hh0;
        ((__nv_bfloat162*)hi)[2 * i + 1] = hh1;
        __nv_bfloat162 ll0{__float2bfloat16(v.x - __bfloat162float(h0)),
                           __float2bfloat16(v.y - __bfloat162float(h1))};
        __nv_bfloat162 ll1{__float2bfloat16(v.z - __bfloat162float(h2)),
                           __float2bfloat16(v.w - __bfloat162float(h3))};
        ((__nv_bfloat162*)lo)[2 * i] = ll0;
        ((__nv_bfloat162*)lo)[2 * i + 1] = ll1;
    }
}

// ---------------- pack Wl|Wr -> Bt[n][k] (transposed), hi/lo split ----------
__global__ void pack_bt_kernel(const float* __restrict__ Wl, const float* __restrict__ Wr,
                               __nv_bfloat16* __restrict__ bhi, __nv_bfloat16* __restrict__ blo,
                               int K, int Nhalf) {
    int idx = blockIdx.x * blockDim.x + threadIdx.x;
    int tot = 2 * Nhalf * K;
    if (idx < tot) {
        int n = idx / K, k = idx % K;
        float v = (n < Nhalf) ? Wl[(size_t)k * Nhalf + n] : Wr[(size_t)k * Nhalf + (n - Nhalf)];
        __nv_bfloat16 h = __float2bfloat16(v);
        bhi[idx] = h;
        blo[idx] = __float2bfloat16(v - __bfloat162float(h));
    }
}

// ---------------- async copy + ldmatrix helpers ----------------
__device__ __forceinline__ void cp16(void* sdst, const void* gsrc, int src_bytes) {
    uint32_t s = (uint32_t)__cvta_generic_to_shared(sdst);
    asm volatile("cp.async.cg.shared.global [%0], [%1], 16, %2;\n"
                 :: "r"(s), "l"(gsrc), "r"(src_bytes));
}
__device__ __forceinline__ void cp_commit() { asm volatile("cp.async.commit_group;\n"); }
__device__ __forceinline__ void cp_wait1() { asm volatile("cp.async.wait_group 1;\n"); }
__device__ __forceinline__ void cp_wait0() { asm volatile("cp.async.wait_group 0;\n"); }

__device__ __forceinline__ void ldsm4(uint32_t r[4], const void* p) {
    uint32_t a = (uint32_t)__cvta_generic_to_shared(p);
    asm volatile("ldmatrix.sync.aligned.m8n8.x4.shared.b16 {%0,%1,%2,%3}, [%4];\n"
                 : "=r"(r[0]), "=r"(r[1]), "=r"(r[2]), "=r"(r[3]) : "r"(a));
}

__device__ __forceinline__ void mma_bf16(float d[4], const uint32_t a[4], const uint32_t b[2]) {
    asm volatile(
        "mma.sync.aligned.m16n8k16.row.col.f32.bf16.bf16.f32 "
        "{%0,%1,%2,%3}, {%4,%5,%6,%7}, {%8,%9}, {%0,%1,%2,%3};\n"
        : "+f"(d[0]), "+f"(d[1]), "+f"(d[2]), "+f"(d[3])
        : "r"(a[0]), "r"(a[1]), "r"(a[2]), "r"(a[3]), "r"(b[0]), "r"(b[1]));
}

// ---------------- tensor-core GEMM, 3-term bf16 split, cp.async, ldmatrix ----
template <int KCHUNKS>
__global__ __launch_bounds__(256, 2)
void mma_gemm_kernel(const __nv_bfloat16* __restrict__ Ahi, const __nv_bfloat16* __restrict__ Alo,
                     const __nv_bfloat16* __restrict__ Bhi, const __nv_bfloat16* __restrict__ Blo,
                     float* __restrict__ C0, float* __restrict__ C1,
                     int M, int ncut, int ld) {
    constexpr int K = KCHUNKS * 16;
    __shared__ __nv_bfloat16 As_hi[2][128][24];
    __shared__ __nv_bfloat16 As_lo[2][128][24];
    __shared__ __nv_bfloat16 Bs_hi[2][128][24];
    __shared__ __nv_bfloat16 Bs_lo[2][128][24];

    int t = threadIdx.x;
    int lane = t & 31, wid = t >> 5;
    int wm = wid & 1, wn = wid >> 1;          // 2 x 4 warp grid
    int group = lane >> 2, tig = lane & 3;
    int m0 = blockIdx.y * 128, n0 = blockIdx.x * 128;

    // ldmatrix per-lane address components
    int a_row = lane & 15;                    // + r0
    int a_col = ((lane >> 4) & 1) * 8;
    int b_row = ((lane >> 4) & 1) * 8 + (lane & 7);  // + c0 (pair base)
    int b_col = ((lane >> 3) & 1) * 8;

    float acc[4][4][4];
#pragma unroll
    for (int i = 0; i < 4; i++)
#pragma unroll
        for (int j = 0; j < 4; j++)
#pragma unroll
            for (int q = 0; q < 4; q++) acc[i][j][q] = 0.f;

    int lrow = t >> 1, lkq = (t & 1) * 8;
    int grow = m0 + lrow;
    int abytes = (grow < M) ? 16 : 0;
    const __nv_bfloat16* pAhi = Ahi + (size_t)(grow < M ? grow : 0) * K + lkq;
    const __nv_bfloat16* pAlo = Alo + (size_t)(grow < M ? grow : 0) * K + lkq;
    const __nv_bfloat16* pBhi = Bhi + (size_t)(n0 + lrow) * K + lkq;
    const __nv_bfloat16* pBlo = Blo + (size_t)(n0 + lrow) * K + lkq;

    cp16(&As_hi[0][lrow][lkq], pAhi, abytes);
    cp16(&As_lo[0][lrow][lkq], pAlo, abytes);
    cp16(&Bs_hi[0][lrow][lkq], pBhi, 16);
    cp16(&Bs_lo[0][lrow][lkq], pBlo, 16);
    cp_commit();

#pragma unroll
    for (int c = 0; c < KCHUNKS; c++) {
        if (c + 1 < KCHUNKS) {
            int st = (c + 1) & 1;
            int ko = (c + 1) * 16;
            cp16(&As_hi[st][lrow][lkq], pAhi + ko, abytes);
            cp16(&As_lo[st][lrow][lkq], pAlo + ko, abytes);
            cp16(&Bs_hi[st][lrow][lkq], pBhi + ko, 16);
            cp16(&Bs_lo[st][lrow][lkq], pBlo + ko, 16);
            cp_commit();
            cp_wait1();
        } else {
            cp_wait0();
        }
        __syncthreads();

        int st = c & 1;
        uint32_t a_hi[4][4], a_lo[4][4];
#pragma unroll
        for (int mf = 0; mf < 4; mf++) {
            int r0 = wm * 64 + mf * 16;
            ldsm4(a_hi[mf], &As_hi[st][r0 + a_row][a_col]);
            ldsm4(a_lo[mf], &As_lo[st][r0 + a_row][a_col]);
        }
        uint32_t b_hi[2][4], b_lo[2][4];   // [pair][4 regs = 2 nf x 2]
#pragma unroll
        for (int p = 0; p < 2; p++) {
            int c0 = wn * 32 + p * 16;
            ldsm4(b_hi[p], &Bs_hi[st][c0 + b_row][b_col]);
            ldsm4(b_lo[p], &Bs_lo[st][c0 + b_row][b_col]);
        }
#pragma unroll
        for (int nf = 0; nf < 4; nf++) {
            const uint32_t* bh = &b_hi[nf >> 1][(nf & 1) * 2];
            const uint32_t* bl = &b_lo[nf >> 1][(nf & 1) * 2];
#pragma unroll
            for (int mf = 0; mf < 4; mf++) {
                mma_bf16(acc[mf][nf], a_hi[mf], bh);
                mma_bf16(acc[mf][nf], a_hi[mf], bl);
                mma_bf16(acc[mf][nf], a_lo[mf], bh);
            }
        }
        __syncthreads();
    }

    // epilogue
#pragma unroll
    for (int mf = 0; mf < 4; mf++) {
        int r = m0 + wm * 64 + mf * 16 + group;
#pragma unroll
        for (int nf = 0; nf < 4; nf++) {
            int cc = n0 + wn * 32 + nf * 8 + tig * 2;
            float* dst = C0;
            int ccol = cc;
            if (cc >= ncut) { dst = C1; ccol = cc - ncut; }
            if (r < M)
                *(float2*)&dst[(size_t)r * ld + ccol] = make_float2(acc[mf][nf][0], acc[mf][nf][1]);
            if (r + 8 < M)
                *(float2*)&dst[(size_t)(r + 8) * ld + ccol] = make_float2(acc[mf][nf][2], acc[mf][nf][3]);
        }
    }
}

#define LRELU(v) ((v) > 0.f ? (v) : 0.2f * (v))

// ---------------- Layer 1 GAT: warp = head, 4 edges/warp, 8 lanes/edge -----
__global__ void gat1_kernel(const float* __restrict__ att1, const float* __restrict__ b1,
                            const float* __restrict__ lng, const float* __restrict__ lnb,
                            int Nn) {
    int i = blockIdx.x;
    int t = threadIdx.x;          // 0..127
    int h = t >> 5;               // warp = head 0..3
    int l = t & 31;
    int s = l >> 3;               // edge slot 0..3
    int c = l & 7;                // channel group (8 ch each)
    __shared__ float sout[256];
    __shared__ float red[4];
    __shared__ float red2[4];

    const float* xrp = g_xr1 + (size_t)i * L1C + h * 64 + c * 8;
    float4 xr0 = ((const float4*)xrp)[0];
    float4 xr1 = ((const float4*)xrp)[1];
    const float* atp = att1 + h * 64 + c * 8;
    float4 at0 = ((const float4*)atp)[0];
    float4 at1 = ((const float4*)atp)[1];

    float acc[8] = {0.f, 0.f, 0.f, 0.f, 0.f, 0.f, 0.f, 0.f};
    float den = 0.f;
    int e0 = g_off[i], deg = g_off[i + 1] - e0;
    for (int base = 0; base < deg; base += 4) {
        int valid = (base + s) < deg;
        int j = valid ? __ldg(&g_src[e0 + base + s]) : 0;
        const float4* px = (const float4*)(g_xl1 + (size_t)j * L1C + h * 64 + c * 8);
        float4 xa0 = px[0], xa1 = px[1];
        float term = LRELU(xa0.x + xr0.x) * at0.x + LRELU(xa0.y + xr0.y) * at0.y
                   + LRELU(xa0.z + xr0.z) * at0.z + LRELU(xa0.w + xr0.w) * at0.w
                   + LRELU(xa1.x + xr1.x) * at1.x + LRELU(xa1.y + xr1.y) * at1.y
                   + LRELU(xa1.z + xr1.z) * at1.z + LRELU(xa1.w + xr1.w) * at1.w;
        term += __shfl_xor_sync(0xffffffffu, term, 1);
        term += __shfl_xor_sync(0xffffffffu, term, 2);
        term += __shfl_xor_sync(0xffffffffu, term, 4);
        float a = valid ? __expf(term) : 0.f;
        acc[0] += a * xa0.x; acc[1] += a * xa0.y; acc[2] += a * xa0.z; acc[3] += a * xa0.w;
        acc[4] += a * xa1.x; acc[5] += a * xa1.y; acc[6] += a * xa1.z; acc[7] += a * xa1.w;
        den += a;
    }
    // cross-slot reduction (slots differ in bit3/bit4 of lane)
#pragma unroll
    for (int k = 0; k < 8; k++) {
        acc[k] += __shfl_xor_sync(0xffffffffu, acc[k], 8);
        acc[k] += __shfl_xor_sync(0xffffffffu, acc[k], 16);
    }
    den += __shfl_xor_sync(0xffffffffu, den, 8);
    den += __shfl_xor_sync(0xffffffffu, den, 16);
    float inv = 1.f / (den + 1e-16f);
    if (s == 0) {
#pragma unroll
        for (int k = 0; k < 8; k++) sout[h * 64 + c * 8 + k] = acc[k] * inv;
    }
    __syncthreads();

    // heads mean + bias + LN (threads t<64 carry data)
    int w = t >> 5, lane = t & 31;
    float val = 0.f;
    if (t < 64)
        val = 0.25f * (sout[t] + sout[t + 64] + sout[t + 128] + sout[t + 192]) + b1[t];

    float v = (t < 64) ? val : 0.f;
#pragma unroll
    for (int o = 16; o; o >>= 1) v += __shfl_xor_sync(0xffffffffu, v, o);
    if (lane == 0) red[w] = v;
    __syncthreads();
    float mu = (red[0] + red[1] + red[2] + red[3]) * (1.f / 64.f);
    float dd = (t < 64) ? (val - mu) : 0.f;
    float v2 = dd * dd;
#pragma unroll
    for (int o = 16; o; o >>= 1) v2 += __shfl_xor_sync(0xffffffffu, v2, o);
    if (lane == 0) red2[w] = v2;
    __syncthreads();
    float var = (red2[0] + red2[1] + red2[2] + red2[3]) * (1.f / 64.f);
    if (t < 64) {
        float y = dd * rsqrtf(var + 1e-5f) * lng[t] + lnb[t];
        g_h[(size_t)i * HID + t] = fmaxf(y, 0.f);
    }
}

// ---------------- Layer 2 GAT: warp per node, 4 edges/warp, LN fused -------
__global__ void gat2_kernel(const float* __restrict__ att2, const float* __restrict__ b2,
                            const float* __restrict__ lng, const float* __restrict__ lnb,
                            float* __restrict__ out, int Nn) {
    int w = threadIdx.x >> 5, l = threadIdx.x & 31;
    int i = blockIdx.x * 4 + w;
    if (i >= Nn) return;
    int s = l >> 3;
    int c = l & 7;
    const float* xl2 = g_xr1;                               // overlay
    const float* xr2 = g_xr1 + (size_t)NMAX * OUTD;         // overlay

    const float* xrp = xr2 + (size_t)i * OUTD + c * 8;
    float4 xr0 = ((const float4*)xrp)[0];
    float4 xr1 = ((const float4*)xrp)[1];
    const float* atp = att2 + c * 8;
    float4 at0 = ((const float4*)atp)[0];
    float4 at1 = ((const float4*)atp)[1];

    float acc[8] = {0.f, 0.f, 0.f, 0.f, 0.f, 0.f, 0.f, 0.f};
    float den = 0.f;
    int e0 = g_off[i], deg = g_off[i + 1] - e0;
    for (int base = 0; base < deg; base += 4) {
        int valid = (base + s) < deg;
        int j = valid ? __ldg(&g_src[e0 + base + s]) : 0;
        const float4* px = (const float4*)(xl2 + (size_t)j * OUTD + c * 8);
        float4 xa0 = px[0], xa1 = px[1];
        float term = LRELU(xa0.x + xr0.x) * at0.x + LRELU(xa0.y + xr0.y) * at0.y
                   + LRELU(xa0.z + xr0.z) * at0.z + LRELU(xa0.w + xr0.w) * at0.w
                   + LRELU(xa1.x + xr1.x) * at1.x + LRELU(xa1.y + xr1.y) * at1.y
                   + LRELU(xa1.z + xr1.z) * at1.z + LRELU(xa1.w + xr1.w) * at1.w;
        term += __shfl_xor_sync(0xffffffffu, term, 1);
        term += __shfl_xor_sync(0xffffffffu, term, 2);
        term += __shfl_xor_sync(0xffffffffu, term, 4);
        float a = valid ? __expf(term) : 0.f;
        acc[0] += a * xa0.x; acc[1] += a * xa0.y; acc[2] += a * xa0.z; acc[3] += a * xa0.w;
        acc[4] += a * xa1.x; acc[5] += a * xa1.y; acc[6] += a * xa1.z; acc[7] += a * xa1.w;
        den += a;
    }
#pragma unroll
    for (int k = 0; k < 8; k++) {
        acc[k] += __shfl_xor_sync(0xffffffffu, acc[k], 8);
        acc[k] += __shfl_xor_sync(0xffffffffu, acc[k], 16);
    }
    den += __shfl_xor_sync(0xffffffffu, den, 8);
    den += __shfl_xor_sync(0xffffffffu, den, 16);
    float inv = 1.f / (den + 1e-16f);

    const float* bp = b2 + c * 8;
    float4 bb0 = ((const float4*)bp)[0];
    float4 bb1 = ((const float4*)bp)[1];
    float v[8];
    v[0] = acc[0] * inv + bb0.x; v[1] = acc[1] * inv + bb0.y;
    v[2] = acc[2] * inv + bb0.z; v[3] = acc[3] * inv + bb0.w;
    v[4] = acc[4] * inv + bb1.x; v[5] = acc[5] * inv + bb1.y;
    v[6] = acc[6] * inv + bb1.z; v[7] = acc[7] * inv + bb1.w;

    // LN: values duplicated 4x across slots -> warp sum = 4 * true sum
    float sum = v[0] + v[1] + v[2] + v[3] + v[4] + v[5] + v[6] + v[7];
#pragma unroll
    for (int o = 16; o; o >>= 1) sum += __shfl_xor_sync(0xffffffffu, sum, o);
    float mu = sum * (1.f / 256.f);
    float q = 0.f;
    float d[8];
#pragma unroll
    for (int k = 0; k < 8; k++) { d[k] = v[k] - mu; q += d[k] * d[k]; }
#pragma unroll
    for (int o = 16; o; o >>= 1) q += __shfl_xor_sync(0xffffffffu, q, o);
    float var = q * (1.f / 256.f);
    float r = rsqrtf(var + 1e-5f);
    if (s == 0) {
        const float* gp = lng + c * 8;
        const float* np = lnb + c * 8;
        float4 gg0 = ((const float4*)gp)[0], gg1 = ((const float4*)gp)[1];
        float4 nn0 = ((const float4*)np)[0], nn1 = ((const float4*)np)[1];
        float4 o0, o1;
        o0.x = d[0] * r * gg0.x + nn0.x; o0.y = d[1] * r * gg0.y + nn0.y;
        o0.z = d[2] * r * gg0.z + nn0.z; o0.w = d[3] * r * gg0.w + nn0.w;
        o1.x = d[4] * r * gg1.x + nn1.x; o1.y = d[5] * r * gg1.y + nn1.y;
        o1.z = d[6] * r * gg1.z + nn1.z; o1.w = d[7] * r * gg1.w + nn1.w;
        float* op = out + (size_t)i * OUTD + c * 8;
        ((float4*)op)[0] = o0;
        ((float4*)op)[1] = o1;
    }
}

// ---------------- launch ----------------
extern "C" void kernel_launch(void* const* d_in, const int* in_sizes, int n_in,
                              void* d_out, int out_size) {
    const float* x    = (const float*)d_in[0];
    const int*   ei   = (const int*)d_in[1];
    const float* W1l  = (const float*)d_in[2];
    const float* W1r  = (const float*)d_in[3];
    const float* att1 = (const float*)d_in[4];
    const float* b1   = (const float*)d_in[5];
    const float* ln1g = (const float*)d_in[6];
    const float* ln1b = (const float*)d_in[7];
    const float* W2l  = (const float*)d_in[8];
    const float* W2r  = (const float*)d_in[9];
    const float* att2 = (const float*)d_in[10];
    const float* b2   = (const float*)d_in[11];
    const float* ln2g = (const float*)d_in[12];
    const float* ln2b = (const float*)d_in[13];
    float* out = (float*)d_out;

    int N = in_sizes[0] / IN_DIM;
    int E = in_sizes[1] / 2;
    if (N > NMAX) N = NMAX;
    if (E > EMAX) E = EMAX;
    int ETOT_RT = E + N;
    int nscan = (N + SCAN_BLK - 1) / SCAN_BLK;

    float *p_xl1, *p_xr1, *p_h;
    __nv_bfloat16 *p_ahi, *p_alo, *p_bhi, *p_blo;
    cudaGetSymbolAddress((void**)&p_xl1, g_xl1);
    cudaGetSymbolAddress((void**)&p_xr1, g_xr1);
    cudaGetSymbolAddress((void**)&p_h,   g_h);
    cudaGetSymbolAddress((void**)&p_ahi, g_ahi);
    cudaGetSymbolAddress((void**)&p_alo, g_alo);
    cudaGetSymbolAddress((void**)&p_bhi, g_bhi);
    cudaGetSymbolAddress((void**)&p_blo, g_blo);
    float* p_xl2 = p_xr1;                              // overlay for layer 2
    float* p_xr2 = p_xr1 + (size_t)NMAX * OUTD;

    // CSR build
    zero_deg_kernel<<<(N + 256) / 256, 256>>>(N);
    hist_kernel<<<(ETOT_RT + 255) / 256, 256>>>(ei, E, N);
    scan1_kernel<<<nscan, SCAN_BLK>>>(N);
    scan2_kernel<<<1, 32>>>(nscan, N);
    scan3_kernel<<<nscan, SCAN_BLK>>>(N);
    scatter_kernel<<<(ETOT_RT + 255) / 256, 256>>>(ei, E, N);

    // Layer 1: split x, pack W, fused tensor-core GEMM -> xl1 | xr1
    {
        int n4 = N * IN_DIM / 4;
        conv_split_kernel<<<(n4 + 255) / 256, 256>>>(x, p_ahi, p_alo, n4);
        pack_bt_kernel<<<(512 * 256 + 255) / 256, 256>>>(W1l, W1r, p_bhi, p_blo, 256, 256);
        dim3 grid(512 / 128, (N + 127) / 128);
        mma_gemm_kernel<16><<<grid, 256>>>(p_ahi, p_alo, p_bhi, p_blo,
                                           p_xl1, p_xr1, N, 256, 256);
    }

    // Layer 1 edge + softmax + aggregate + heads-mean + bias + LN + ReLU
    gat1_kernel<<<N, 128>>>(att1, b1, ln1g, ln1b, N);

    // Layer 2: split h, pack W2, fused GEMM -> xl2 | xr2 (overlay)
    {
        int n4 = N * HID / 4;
        conv_split_kernel<<<(n4 + 255) / 256, 256>>>(p_h, p_ahi, p_alo, n4);
        pack_bt_kernel<<<(128 * 64 + 255) / 256, 256>>>(W2l, W2r, p_bhi, p_blo, 64, 64);
        dim3 grid(128 / 128, (N + 127) / 128);
        mma_gemm_kernel<4><<<grid, 256>>>(p_ahi, p_alo, p_bhi, p_blo,
                                          p_xl2, p_xr2, N, 64, 64);
    }

    // Layer 2 edge + softmax + aggregate + bias + LN -> out
    gat2_kernel<<<(N + 3) / 4, 128>>>(att2, b2, ln2g, ln2b, out, N);
}

// round 7
// speedup vs baseline: 1.9228x; 1.0266x over previous
#include <cuda_runtime.h>
#include <cuda_bf16.h>
#include <math.h>
#include <stdint.h>

#define NMAX 50000
#define EMAX 800000
#define ETOTAL (EMAX + NMAX)
#define IN_DIM 256
#define HID 64
#define L1C 256
#define OUTD 64
#define SCAN_BLK 1024
#define NSCAN ((NMAX + SCAN_BLK - 1) / SCAN_BLK)

// ---------------- scratch (device globals; allocation-free) ----------------
__device__ float g_xl1[(size_t)NMAX * L1C];
__device__ float g_xr1[(size_t)NMAX * L1C];   // reused for layer2 xl2/xr2
__device__ float g_h[(size_t)NMAX * HID];
__device__ __nv_bfloat16 g_ahi[(size_t)NMAX * 256];
__device__ __nv_bfloat16 g_alo[(size_t)NMAX * 256];
__device__ __nv_bfloat16 g_bhi[512 * 256];
__device__ __nv_bfloat16 g_blo[512 * 256];
__device__ __nv_bfloat16 g_bhi2[128 * 64];
__device__ __nv_bfloat16 g_blo2[128 * 64];
__device__ int   g_deg[NMAX + 1];
__device__ int   g_off[NMAX + 1];
__device__ int   g_cur[NMAX];
__device__ int   g_src[ETOTAL];
__device__ int   g_bsum[NSCAN + 1];

// ---------------- CSR build ----------------
__global__ void zero_deg_kernel(int n) {
    int i = blockIdx.x * blockDim.x + threadIdx.x;
    if (i <= n) g_deg[i] = 0;
}

__global__ void hist_kernel(const int* __restrict__ ei, int E, int n) {
    int e = blockIdx.x * blockDim.x + threadIdx.x;
    int tot = E + n;
    if (e < tot) {
        int d = (e < E) ? ei[E + e] : (e - E);
        if (d < 0) d = 0;
        if (d >= n) d = n - 1;
        atomicAdd(&g_deg[d], 1);
    }
}

// phase 1: per-block exclusive scan of deg -> off (local), block sums -> g_bsum
__global__ void scan1_kernel(int n) {
    __shared__ int sh[SCAN_BLK];
    int tid = threadIdx.x;
    int idx = blockIdx.x * SCAN_BLK + tid;
    int v = (idx < n) ? g_deg[idx] : 0;
    sh[tid] = v;
    __syncthreads();
    for (int d = 1; d < SCAN_BLK; d <<= 1) {
        int t = sh[tid];
        int add = (tid >= d) ? sh[tid - d] : 0;
        __syncthreads();
        sh[tid] = t + add;
        __syncthreads();
    }
    if (idx < n) g_off[idx] = sh[tid] - v;   // exclusive within block
    if (tid == SCAN_BLK - 1) g_bsum[blockIdx.x] = sh[tid];
}

// phase 2: scan of block sums (<=64 entries) via shfl + smem
__global__ void scan2_kernel(int nb, int n) {
    __shared__ int wsum[2];
    int t = threadIdx.x;              // 64 threads
    int w = t >> 5, l = t & 31;
    int v = (t < nb) ? g_bsum[t] : 0;
    int sc = v;
#pragma unroll
    for (int d = 1; d < 32; d <<= 1) {
        int u = __shfl_up_sync(0xffffffffu, sc, d);
        if (l >= d) sc += u;
    }
    if (l == 31) wsum[w] = sc;
    __syncthreads();
    int base = (w == 1) ? wsum[0] : 0;
    if (t < nb) g_bsum[t] = sc - v + base;          // exclusive
    if (t == nb - 1 || (nb > 64 && t == 63)) { /* nothing */ }
    if (t == 0) {
        // total for g_off[n]
        int tot = wsum[0] + ((nb > 32) ? wsum[1] : 0);
        if (nb <= 32) tot = wsum[0];
        g_off[n] = tot;
    }
}

// phase 3: add block offsets, init cursor
__global__ void scan3_kernel(int n) {
    int idx = blockIdx.x * SCAN_BLK + threadIdx.x;
    if (idx < n) {
        int o = g_off[idx] + g_bsum[blockIdx.x];
        g_off[idx] = o;
        g_cur[idx] = o;
    }
}

__global__ void scatter_kernel(const int* __restrict__ ei, int E, int n) {
    int e = blockIdx.x * blockDim.x + threadIdx.x;
    int tot = E + n;
    if (e < tot) {
        int s, d;
        if (e < E) { s = ei[e]; d = ei[E + e]; }
        else       { s = d = e - E; }
        if (s < 0) s = 0; if (s >= n) s = n - 1;
        if (d < 0) d = 0; if (d >= n) d = n - 1;
        int pos = atomicAdd(&g_cur[d], 1);
        if (pos >= 0 && pos < ETOTAL) g_src[pos] = s;
    }
}

// ---------------- fp32 -> (hi, lo) bf16 split ----------------
__global__ void conv_split_kernel(const float* __restrict__ in,
                                  __nv_bfloat16* __restrict__ hi,
                                  __nv_bfloat16* __restrict__ lo, int n4) {
    int i = blockIdx.x * blockDim.x + threadIdx.x;
    if (i < n4) {
        float4 v = ((const float4*)in)[i];
        __nv_bfloat16 h0 = __float2bfloat16(v.x);
        __nv_bfloat16 h1 = __float2bfloat16(v.y);
        __nv_bfloat16 h2 = __float2bfloat16(v.z);
        __nv_bfloat16 h3 = __float2bfloat16(v.w);
        __nv_bfloat162 hh0{h0, h1}, hh1{h2, h3};
        ((__nv_bfloat162*)hi)[2 * i] = hh0;
        ((__nv_bfloat162*)hi)[2 * i + 1] = hh1;
        __nv_bfloat162 ll0{__float2bfloat16(v.x - __bfloat162float(h0)),
                           __float2bfloat16(v.y - __bfloat162float(h1))};
        __nv_bfloat162 ll1{__float2bfloat16(v.z - __bfloat162float(h2)),
                           __float2bfloat16(v.w - __bfloat162float(h3))};
        ((__nv_bfloat162*)lo)[2 * i] = ll0;
        ((__nv_bfloat162*)lo)[2 * i + 1] = ll1;
    }
}

// ---------------- pack Wl|Wr -> Bt[n][k] (transposed), hi/lo split ----------
__global__ void pack_bt_kernel(const float* __restrict__ Wl, const float* __restrict__ Wr,
                               __nv_bfloat16* __restrict__ bhi, __nv_bfloat16* __restrict__ blo,
                               int K, int Nhalf) {
    int idx = blockIdx.x * blockDim.x + threadIdx.x;
    int tot = 2 * Nhalf * K;
    if (idx < tot) {
        int n = idx / K, k = idx % K;
        float v = (n < Nhalf) ? Wl[(size_t)k * Nhalf + n] : Wr[(size_t)k * Nhalf + (n - Nhalf)];
        __nv_bfloat16 h = __float2bfloat16(v);
        bhi[idx] = h;
        blo[idx] = __float2bfloat16(v - __bfloat162float(h));
    }
}

// ---------------- async copy + ldmatrix helpers ----------------
__device__ __forceinline__ void cp16(void* sdst, const void* gsrc, int src_bytes) {
    uint32_t s = (uint32_t)__cvta_generic_to_shared(sdst);
    asm volatile("cp.async.cg.shared.global [%0], [%1], 16, %2;\n"
                 :: "r"(s), "l"(gsrc), "r"(src_bytes));
}
__device__ __forceinline__ void cp_commit() { asm volatile("cp.async.commit_group;\n"); }
__device__ __forceinline__ void cp_wait1() { asm volatile("cp.async.wait_group 1;\n"); }
__device__ __forceinline__ void cp_wait0() { asm volatile("cp.async.wait_group 0;\n"); }

__device__ __forceinline__ void ldsm4(uint32_t r[4], const void* p) {
    uint32_t a = (uint32_t)__cvta_generic_to_shared(p);
    asm volatile("ldmatrix.sync.aligned.m8n8.x4.shared.b16 {%0,%1,%2,%3}, [%4];\n"
                 : "=r"(r[0]), "=r"(r[1]), "=r"(r[2]), "=r"(r[3]) : "r"(a));
}

__device__ __forceinline__ void mma_bf16(float d[4], const uint32_t a[4], const uint32_t b[2]) {
    asm volatile(
        "mma.sync.aligned.m16n8k16.row.col.f32.bf16.bf16.f32 "
        "{%0,%1,%2,%3}, {%4,%5,%6,%7}, {%8,%9}, {%0,%1,%2,%3};\n"
        : "+f"(d[0]), "+f"(d[1]), "+f"(d[2]), "+f"(d[3])
        : "r"(a[0]), "r"(a[1]), "r"(a[2]), "r"(a[3]), "r"(b[0]), "r"(b[1]));
}

// ---------------- tensor-core GEMM, 3-term bf16 split, cp.async, ldmatrix ----
template <int KCHUNKS>
__global__ __launch_bounds__(256, 2)
void mma_gemm_kernel(const __nv_bfloat16* __restrict__ Ahi, const __nv_bfloat16* __restrict__ Alo,
                     const __nv_bfloat16* __restrict__ Bhi, const __nv_bfloat16* __restrict__ Blo,
                     float* __restrict__ C0, float* __restrict__ C1,
                     int M, int ncut, int ld) {
    constexpr int K = KCHUNKS * 16;
    __shared__ __nv_bfloat16 As_hi[2][128][24];
    __shared__ __nv_bfloat16 As_lo[2][128][24];
    __shared__ __nv_bfloat16 Bs_hi[2][128][24];
    __shared__ __nv_bfloat16 Bs_lo[2][128][24];

    int t = threadIdx.x;
    int lane = t & 31, wid = t >> 5;
    int wm = wid & 1, wn = wid >> 1;          // 2 x 4 warp grid
    int group = lane >> 2, tig = lane & 3;
    int m0 = blockIdx.y * 128, n0 = blockIdx.x * 128;

    int a_row = lane & 15;
    int a_col = ((lane >> 4) & 1) * 8;
    int b_row = ((lane >> 4) & 1) * 8 + (lane & 7);
    int b_col = ((lane >> 3) & 1) * 8;

    float acc[4][4][4];
#pragma unroll
    for (int i = 0; i < 4; i++)
#pragma unroll
        for (int j = 0; j < 4; j++)
#pragma unroll
            for (int q = 0; q < 4; q++) acc[i][j][q] = 0.f;

    int lrow = t >> 1, lkq = (t & 1) * 8;
    int grow = m0 + lrow;
    int abytes = (grow < M) ? 16 : 0;
    const __nv_bfloat16* pAhi = Ahi + (size_t)(grow < M ? grow : 0) * K + lkq;
    const __nv_bfloat16* pAlo = Alo + (size_t)(grow < M ? grow : 0) * K + lkq;
    const __nv_bfloat16* pBhi = Bhi + (size_t)(n0 + lrow) * K + lkq;
    const __nv_bfloat16* pBlo = Blo + (size_t)(n0 + lrow) * K + lkq;

    cp16(&As_hi[0][lrow][lkq], pAhi, abytes);
    cp16(&As_lo[0][lrow][lkq], pAlo, abytes);
    cp16(&Bs_hi[0][lrow][lkq], pBhi, 16);
    cp16(&Bs_lo[0][lrow][lkq], pBlo, 16);
    cp_commit();

#pragma unroll
    for (int c = 0; c < KCHUNKS; c++) {
        if (c + 1 < KCHUNKS) {
            int st = (c + 1) & 1;
            int ko = (c + 1) * 16;
            cp16(&As_hi[st][lrow][lkq], pAhi + ko, abytes);
            cp16(&As_lo[st][lrow][lkq], pAlo + ko, abytes);
            cp16(&Bs_hi[st][lrow][lkq], pBhi + ko, 16);
            cp16(&Bs_lo[st][lrow][lkq], pBlo + ko, 16);
            cp_commit();
            cp_wait1();
        } else {
            cp_wait0();
        }
        __syncthreads();

        int st = c & 1;
        uint32_t a_hi[4][4], a_lo[4][4];
#pragma unroll
        for (int mf = 0; mf < 4; mf++) {
            int r0 = wm * 64 + mf * 16;
            ldsm4(a_hi[mf], &As_hi[st][r0 + a_row][a_col]);
            ldsm4(a_lo[mf], &As_lo[st][r0 + a_row][a_col]);
        }
        uint32_t b_hi[2][4], b_lo[2][4];
#pragma unroll
        for (int p = 0; p < 2; p++) {
            int c0 = wn * 32 + p * 16;
            ldsm4(b_hi[p], &Bs_hi[st][c0 + b_row][b_col]);
            ldsm4(b_lo[p], &Bs_lo[st][c0 + b_row][b_col]);
        }
#pragma unroll
        for (int nf = 0; nf < 4; nf++) {
            const uint32_t* bh = &b_hi[nf >> 1][(nf & 1) * 2];
            const uint32_t* bl = &b_lo[nf >> 1][(nf & 1) * 2];
#pragma unroll
            for (int mf = 0; mf < 4; mf++) {
                mma_bf16(acc[mf][nf], a_hi[mf], bh);
                mma_bf16(acc[mf][nf], a_hi[mf], bl);
                mma_bf16(acc[mf][nf], a_lo[mf], bh);
            }
        }
        __syncthreads();
    }

#pragma unroll
    for (int mf = 0; mf < 4; mf++) {
        int r = m0 + wm * 64 + mf * 16 + group;
#pragma unroll
        for (int nf = 0; nf < 4; nf++) {
            int cc = n0 + wn * 32 + nf * 8 + tig * 2;
            float* dst = C0;
            int ccol = cc;
            if (cc >= ncut) { dst = C1; ccol = cc - ncut; }
            if (r < M)
                *(float2*)&dst[(size_t)r * ld + ccol] = make_float2(acc[mf][nf][0], acc[mf][nf][1]);
            if (r + 8 < M)
                *(float2*)&dst[(size_t)(r + 8) * ld + ccol] = make_float2(acc[mf][nf][2], acc[mf][nf][3]);
        }
    }
}

#define LRELU(v) ((v) > 0.f ? (v) : 0.2f * (v))

// ---------------- Layer 1 GAT + fused bf16 split of hidden -----------------
__global__ void gat1_kernel(const float* __restrict__ att1, const float* __restrict__ b1,
                            const float* __restrict__ lng, const float* __restrict__ lnb,
                            int Nn) {
    int i = blockIdx.x;
    int t = threadIdx.x;          // 0..127
    int h = t >> 5;               // warp = head 0..3
    int l = t & 31;
    int s = l >> 3;               // edge slot 0..3
    int c = l & 7;                // channel group (8 ch each)
    __shared__ float sout[256];
    __shared__ float red[4];
    __shared__ float red2[4];

    const float* xrp = g_xr1 + (size_t)i * L1C + h * 64 + c * 8;
    float4 xr0 = ((const float4*)xrp)[0];
    float4 xr1 = ((const float4*)xrp)[1];
    const float* atp = att1 + h * 64 + c * 8;
    float4 at0 = ((const float4*)atp)[0];
    float4 at1 = ((const float4*)atp)[1];

    float acc[8] = {0.f, 0.f, 0.f, 0.f, 0.f, 0.f, 0.f, 0.f};
    float den = 0.f;
    int e0 = g_off[i], deg = g_off[i + 1] - e0;
    for (int base = 0; base < deg; base += 4) {
        int valid = (base + s) < deg;
        int j = valid ? __ldg(&g_src[e0 + base + s]) : 0;
        const float4* px = (const float4*)(g_xl1 + (size_t)j * L1C + h * 64 + c * 8);
        float4 xa0 = px[0], xa1 = px[1];
        float term = LRELU(xa0.x + xr0.x) * at0.x + LRELU(xa0.y + xr0.y) * at0.y
                   + LRELU(xa0.z + xr0.z) * at0.z + LRELU(xa0.w + xr0.w) * at0.w
                   + LRELU(xa1.x + xr1.x) * at1.x + LRELU(xa1.y + xr1.y) * at1.y
                   + LRELU(xa1.z + xr1.z) * at1.z + LRELU(xa1.w + xr1.w) * at1.w;
        term += __shfl_xor_sync(0xffffffffu, term, 1);
        term += __shfl_xor_sync(0xffffffffu, term, 2);
        term += __shfl_xor_sync(0xffffffffu, term, 4);
        float a = valid ? __expf(term) : 0.f;
        acc[0] += a * xa0.x; acc[1] += a * xa0.y; acc[2] += a * xa0.z; acc[3] += a * xa0.w;
        acc[4] += a * xa1.x; acc[5] += a * xa1.y; acc[6] += a * xa1.z; acc[7] += a * xa1.w;
        den += a;
    }
#pragma unroll
    for (int k = 0; k < 8; k++) {
        acc[k] += __shfl_xor_sync(0xffffffffu, acc[k], 8);
        acc[k] += __shfl_xor_sync(0xffffffffu, acc[k], 16);
    }
    den += __shfl_xor_sync(0xffffffffu, den, 8);
    den += __shfl_xor_sync(0xffffffffu, den, 16);
    float inv = 1.f / (den + 1e-16f);
    if (s == 0) {
#pragma unroll
        for (int k = 0; k < 8; k++) sout[h * 64 + c * 8 + k] = acc[k] * inv;
    }
    __syncthreads();

    int w = t >> 5, lane = t & 31;
    float val = 0.f;
    if (t < 64)
        val = 0.25f * (sout[t] + sout[t + 64] + sout[t + 128] + sout[t + 192]) + b1[t];

    float v = (t < 64) ? val : 0.f;
#pragma unroll
    for (int o = 16; o; o >>= 1) v += __shfl_xor_sync(0xffffffffu, v, o);
    if (lane == 0) red[w] = v;
    __syncthreads();
    float mu = (red[0] + red[1] + red[2] + red[3]) * (1.f / 64.f);
    float dd = (t < 64) ? (val - mu) : 0.f;
    float v2 = dd * dd;
#pragma unroll
    for (int o = 16; o; o >>= 1) v2 += __shfl_xor_sync(0xffffffffu, v2, o);
    if (lane == 0) red2[w] = v2;
    __syncthreads();
    float var = (red2[0] + red2[1] + red2[2] + red2[3]) * (1.f / 64.f);
    if (t < 64) {
        float y = dd * rsqrtf(var + 1e-5f) * lng[t] + lnb[t];
        float hv = fmaxf(y, 0.f);
        g_h[(size_t)i * HID + t] = hv;
        // fused bf16 hi/lo split for layer-2 GEMM A operand
        __nv_bfloat16 hb = __float2bfloat16(hv);
        g_ahi[(size_t)i * HID + t] = hb;
        g_alo[(size_t)i * HID + t] = __float2bfloat16(hv - __bfloat162float(hb));
    }
}

// ---------------- Layer 2 GAT: warp per node, 4 edges/warp, LN fused -------
__global__ void gat2_kernel(const float* __restrict__ att2, const float* __restrict__ b2,
                            const float* __restrict__ lng, const float* __restrict__ lnb,
                            float* __restrict__ out, int Nn) {
    int w = threadIdx.x >> 5, l = threadIdx.x & 31;
    int i = blockIdx.x * 4 + w;
    if (i >= Nn) return;
    int s = l >> 3;
    int c = l & 7;
    const float* xl2 = g_xr1;                               // overlay
    const float* xr2 = g_xr1 + (size_t)NMAX * OUTD;         // overlay

    const float* xrp = xr2 + (size_t)i * OUTD + c * 8;
    float4 xr0 = ((const float4*)xrp)[0];
    float4 xr1 = ((const float4*)xrp)[1];
    const float* atp = att2 + c * 8;
    float4 at0 = ((const float4*)atp)[0];
    float4 at1 = ((const float4*)atp)[1];

    float acc[8] = {0.f, 0.f, 0.f, 0.f, 0.f, 0.f, 0.f, 0.f};
    float den = 0.f;
    int e0 = g_off[i], deg = g_off[i + 1] - e0;
    for (int base = 0; base < deg; base += 4) {
        int valid = (base + s) < deg;
        int j = valid ? __ldg(&g_src[e0 + base + s]) : 0;
        const float4* px = (const float4*)(xl2 + (size_t)j * OUTD + c * 8);
        float4 xa0 = px[0], xa1 = px[1];
        float term = LRELU(xa0.x + xr0.x) * at0.x + LRELU(xa0.y + xr0.y) * at0.y
                   + LRELU(xa0.z + xr0.z) * at0.z + LRELU(xa0.w + xr0.w) * at0.w
                   + LRELU(xa1.x + xr1.x) * at1.x + LRELU(xa1.y + xr1.y) * at1.y
                   + LRELU(xa1.z + xr1.z) * at1.z + LRELU(xa1.w + xr1.w) * at1.w;
        term += __shfl_xor_sync(0xffffffffu, term, 1);
        term += __shfl_xor_sync(0xffffffffu, term, 2);
        term += __shfl_xor_sync(0xffffffffu, term, 4);
        float a = valid ? __expf(term) : 0.f;
        acc[0] += a * xa0.x; acc[1] += a * xa0.y; acc[2] += a * xa0.z; acc[3] += a * xa0.w;
        acc[4] += a * xa1.x; acc[5] += a * xa1.y; acc[6] += a * xa1.z; acc[7] += a * xa1.w;
        den += a;
    }
#pragma unroll
    for (int k = 0; k < 8; k++) {
        acc[k] += __shfl_xor_sync(0xffffffffu, acc[k], 8);
        acc[k] += __shfl_xor_sync(0xffffffffu, acc[k], 16);
    }
    den += __shfl_xor_sync(0xffffffffu, den, 8);
    den += __shfl_xor_sync(0xffffffffu, den, 16);
    float inv = 1.f / (den + 1e-16f);

    const float* bp = b2 + c * 8;
    float4 bb0 = ((const float4*)bp)[0];
    float4 bb1 = ((const float4*)bp)[1];
    float v[8];
    v[0] = acc[0] * inv + bb0.x; v[1] = acc[1] * inv + bb0.y;
    v[2] = acc[2] * inv + bb0.z; v[3] = acc[3] * inv + bb0.w;
    v[4] = acc[4] * inv + bb1.x; v[5] = acc[5] * inv + bb1.y;
    v[6] = acc[6] * inv + bb1.z; v[7] = acc[7] * inv + bb1.w;

    float sum = v[0] + v[1] + v[2] + v[3] + v[4] + v[5] + v[6] + v[7];
#pragma unroll
    for (int o = 16; o; o >>= 1) sum += __shfl_xor_sync(0xffffffffu, sum, o);
    float mu = sum * (1.f / 256.f);
    float q = 0.f;
    float d[8];
#pragma unroll
    for (int k = 0; k < 8; k++) { d[k] = v[k] - mu; q += d[k] * d[k]; }
#pragma unroll
    for (int o = 16; o; o >>= 1) q += __shfl_xor_sync(0xffffffffu, q, o);
    float var = q * (1.f / 256.f);
    float r = rsqrtf(var + 1e-5f);
    if (s == 0) {
        const float* gp = lng + c * 8;
        const float* np = lnb + c * 8;
        float4 gg0 = ((const float4*)gp)[0], gg1 = ((const float4*)gp)[1];
        float4 nn0 = ((const float4*)np)[0], nn1 = ((const float4*)np)[1];
        float4 o0, o1;
        o0.x = d[0] * r * gg0.x + nn0.x; o0.y = d[1] * r * gg0.y + nn0.y;
        o0.z = d[2] * r * gg0.z + nn0.z; o0.w = d[3] * r * gg0.w + nn0.w;
        o1.x = d[4] * r * gg1.x + nn1.x; o1.y = d[5] * r * gg1.y + nn1.y;
        o1.z = d[6] * r * gg1.z + nn1.z; o1.w = d[7] * r * gg1.w + nn1.w;
        float* op = out + (size_t)i * OUTD + c * 8;
        ((float4*)op)[0] = o0;
        ((float4*)op)[1] = o1;
    }
}

// ---------------- launch ----------------
extern "C" void kernel_launch(void* const* d_in, const int* in_sizes, int n_in,
                              void* d_out, int out_size) {
    const float* x    = (const float*)d_in[0];
    const int*   ei   = (const int*)d_in[1];
    const float* W1l  = (const float*)d_in[2];
    const float* W1r  = (const float*)d_in[3];
    const float* att1 = (const float*)d_in[4];
    const float* b1   = (const float*)d_in[5];
    const float* ln1g = (const float*)d_in[6];
    const float* ln1b = (const float*)d_in[7];
    const float* W2l  = (const float*)d_in[8];
    const float* W2r  = (const float*)d_in[9];
    const float* att2 = (const float*)d_in[10];
    const float* b2   = (const float*)d_in[11];
    const float* ln2g = (const float*)d_in[12];
    const float* ln2b = (const float*)d_in[13];
    float* out = (float*)d_out;

    int N = in_sizes[0] / IN_DIM;
    int E = in_sizes[1] / 2;
    if (N > NMAX) N = NMAX;
    if (E > EMAX) E = EMAX;
    int ETOT_RT = E + N;
    int nscan = (N + SCAN_BLK - 1) / SCAN_BLK;

    float *p_xl1, *p_xr1, *p_h;
    __nv_bfloat16 *p_ahi, *p_alo, *p_bhi, *p_blo, *p_bhi2, *p_blo2;
    cudaGetSymbolAddress((void**)&p_xl1, g_xl1);
    cudaGetSymbolAddress((void**)&p_xr1, g_xr1);
    cudaGetSymbolAddress((void**)&p_h,   g_h);
    cudaGetSymbolAddress((void**)&p_ahi, g_ahi);
    cudaGetSymbolAddress((void**)&p_alo, g_alo);
    cudaGetSymbolAddress((void**)&p_bhi, g_bhi);
    cudaGetSymbolAddress((void**)&p_blo, g_blo);
    cudaGetSymbolAddress((void**)&p_bhi2, g_bhi2);
    cudaGetSymbolAddress((void**)&p_blo2, g_blo2);
    float* p_xl2 = p_xr1;                              // overlay for layer 2
    float* p_xr2 = p_xr1 + (size_t)NMAX * OUTD;

    // streams/events created once (first call is uncaptured correctness run)
    static cudaStream_t s2 = nullptr;
    static cudaEvent_t ev_fork = nullptr, ev_g1 = nullptr;
    if (!s2) {
        cudaStreamCreateWithFlags(&s2, cudaStreamNonBlocking);
        cudaEventCreateWithFlags(&ev_fork, cudaEventDisableTiming);
        cudaEventCreateWithFlags(&ev_g1, cudaEventDisableTiming);
    }

    // fork: s2 joins the (possibly capturing) default stream
    cudaEventRecord(ev_fork, 0);
    cudaStreamWaitEvent(s2, ev_fork, 0);

    // ---- stream s2: layer-1 GEMM chain (independent of graph) ----
    {
        int n4 = N * IN_DIM / 4;
        conv_split_kernel<<<(n4 + 255) / 256, 256, 0, s2>>>(x, p_ahi, p_alo, n4);
        pack_bt_kernel<<<(512 * 256 + 255) / 256, 256, 0, s2>>>(W1l, W1r, p_bhi, p_blo, 256, 256);
        pack_bt_kernel<<<(128 * 64 + 255) / 256, 256, 0, s2>>>(W2l, W2r, p_bhi2, p_blo2, 64, 64);
        dim3 grid(512 / 128, (N + 127) / 128);
        mma_gemm_kernel<16><<<grid, 256, 0, s2>>>(p_ahi, p_alo, p_bhi, p_blo,
                                                  p_xl1, p_xr1, N, 256, 256);
        cudaEventRecord(ev_g1, s2);
    }

    // ---- default stream: CSR build (runs concurrently) ----
    zero_deg_kernel<<<(N + 256) / 256, 256>>>(N);
    hist_kernel<<<(ETOT_RT + 255) / 256, 256>>>(ei, E, N);
    scan1_kernel<<<nscan, SCAN_BLK>>>(N);
    scan2_kernel<<<1, 64>>>(nscan, N);
    scan3_kernel<<<nscan, SCAN_BLK>>>(N);
    scatter_kernel<<<(ETOT_RT + 255) / 256, 256>>>(ei, E, N);

    // join: gat1 needs CSR (default) + GEMM1 (s2)
    cudaStreamWaitEvent(0, ev_g1, 0);

    // Layer 1 edge pass (+ fused bf16 split of hidden into g_ahi/g_alo)
    gat1_kernel<<<N, 128>>>(att1, b1, ln1g, ln1b, N);

    // Layer 2 GEMM: [N,64] x [64,128] -> xl2 | xr2 (overlay)
    {
        dim3 grid(1, (N + 127) / 128);
        mma_gemm_kernel<4><<<grid, 256>>>(p_ahi, p_alo, p_bhi2, p_blo2,
                                          p_xl2, p_xr2, N, 64, 64);
    }

    // Layer 2 edge + softmax + aggregate + bias + LN -> out
    gat2_kernel<<<(N + 3) / 4, 128>>>(att2, b2, ln2g, ln2b, out, N);
}

// round 8
// speedup vs baseline: 1.9998x; 1.0401x over previous
#include <cuda_runtime.h>
#include <cuda_bf16.h>
#include <math.h>
#include <stdint.h>

#define NMAX 50000
#define EMAX 800000
#define ETOTAL (EMAX + NMAX)
#define IN_DIM 256
#define HID 64
#define L1C 256
#define OUTD 64
#define SCAN_BLK 1024
#define NSCAN ((NMAX + SCAN_BLK - 1) / SCAN_BLK)

// dynamic smem for GEMM: 3 stages x 4 arrays x 128 rows x 24 cols bf16
#define GEMM_STAGE_ELEMS (4 * 128 * 24)
#define GEMM_SMEM_BYTES (3 * GEMM_STAGE_ELEMS * 2)

// ---------------- scratch (device globals; allocation-free) ----------------
__device__ float g_xl1[(size_t)NMAX * L1C];
__device__ float g_xr1[(size_t)NMAX * L1C];   // reused for layer2 xl2/xr2
__device__ float g_h[(size_t)NMAX * HID];
__device__ __nv_bfloat16 g_ahi[(size_t)NMAX * 256];
__device__ __nv_bfloat16 g_alo[(size_t)NMAX * 256];
__device__ __nv_bfloat16 g_bhi[512 * 256];
__device__ __nv_bfloat16 g_blo[512 * 256];
__device__ __nv_bfloat16 g_bhi2[128 * 64];
__device__ __nv_bfloat16 g_blo2[128 * 64];
__device__ int   g_deg[NMAX + 1];
__device__ int   g_off[NMAX + 1];
__device__ int   g_cur[NMAX];
__device__ int   g_src[ETOTAL];
__device__ int   g_bsum[NSCAN + 1];

// ---------------- CSR build ----------------
__global__ void zero_deg_kernel(int n) {
    int i = blockIdx.x * blockDim.x + threadIdx.x;
    if (i <= n) g_deg[i] = 0;
}

__global__ void hist_kernel(const int* __restrict__ ei, int E, int n) {
    int e = blockIdx.x * blockDim.x + threadIdx.x;
    int tot = E + n;
    if (e < tot) {
        int d = (e < E) ? ei[E + e] : (e - E);
        if (d < 0) d = 0;
        if (d >= n) d = n - 1;
        atomicAdd(&g_deg[d], 1);
    }
}

__global__ void scan1_kernel(int n) {
    __shared__ int sh[SCAN_BLK];
    int tid = threadIdx.x;
    int idx = blockIdx.x * SCAN_BLK + tid;
    int v = (idx < n) ? g_deg[idx] : 0;
    sh[tid] = v;
    __syncthreads();
    for (int d = 1; d < SCAN_BLK; d <<= 1) {
        int t = sh[tid];
        int add = (tid >= d) ? sh[tid - d] : 0;
        __syncthreads();
        sh[tid] = t + add;
        __syncthreads();
    }
    if (idx < n) g_off[idx] = sh[tid] - v;   // exclusive within block
    if (tid == SCAN_BLK - 1) g_bsum[blockIdx.x] = sh[tid];
}

__global__ void scan2_kernel(int nb, int n) {
    __shared__ int wsum[2];
    int t = threadIdx.x;              // 64 threads
    int w = t >> 5, l = t & 31;
    int v = (t < nb) ? g_bsum[t] : 0;
    int sc = v;
#pragma unroll
    for (int d = 1; d < 32; d <<= 1) {
        int u = __shfl_up_sync(0xffffffffu, sc, d);
        if (l >= d) sc += u;
    }
    if (l == 31) wsum[w] = sc;
    __syncthreads();
    int base = (w == 1) ? wsum[0] : 0;
    if (t < nb) g_bsum[t] = sc - v + base;          // exclusive
    if (t == 0) {
        int tot = wsum[0] + ((nb > 32) ? wsum[1] : 0);
        if (nb <= 32) tot = wsum[0];
        g_off[n] = tot;
    }
}

__global__ void scan3_kernel(int n) {
    int idx = blockIdx.x * SCAN_BLK + threadIdx.x;
    if (idx < n) {
        int o = g_off[idx] + g_bsum[blockIdx.x];
        g_off[idx] = o;
        g_cur[idx] = o;
    }
}

__global__ void scatter_kernel(const int* __restrict__ ei, int E, int n) {
    int e = blockIdx.x * blockDim.x + threadIdx.x;
    int tot = E + n;
    if (e < tot) {
        int s, d;
        if (e < E) { s = ei[e]; d = ei[E + e]; }
        else       { s = d = e - E; }
        if (s < 0) s = 0; if (s >= n) s = n - 1;
        if (d < 0) d = 0; if (d >= n) d = n - 1;
        int pos = atomicAdd(&g_cur[d], 1);
        if (pos >= 0 && pos < ETOTAL) g_src[pos] = s;
    }
}

// ---------------- fp32 -> (hi, lo) bf16 split ----------------
__global__ void conv_split_kernel(const float* __restrict__ in,
                                  __nv_bfloat16* __restrict__ hi,
                                  __nv_bfloat16* __restrict__ lo, int n4) {
    int i = blockIdx.x * blockDim.x + threadIdx.x;
    if (i < n4) {
        float4 v = ((const float4*)in)[i];
        __nv_bfloat16 h0 = __float2bfloat16(v.x);
        __nv_bfloat16 h1 = __float2bfloat16(v.y);
        __nv_bfloat16 h2 = __float2bfloat16(v.z);
        __nv_bfloat16 h3 = __float2bfloat16(v.w);
        __nv_bfloat162 hh0{h0, h1}, hh1{h2, h3};
        ((__nv_bfloat162*)hi)[2 * i] = hh0;
        ((__nv_bfloat162*)hi)[2 * i + 1] = hh1;
        __nv_bfloat162 ll0{__float2bfloat16(v.x - __bfloat162float(h0)),
                           __float2bfloat16(v.y - __bfloat162float(h1))};
        __nv_bfloat162 ll1{__float2bfloat16(v.z - __bfloat162float(h2)),
                           __float2bfloat16(v.w - __bfloat162float(h3))};
        ((__nv_bfloat162*)lo)[2 * i] = ll0;
        ((__nv_bfloat162*)lo)[2 * i + 1] = ll1;
    }
}

// ---------------- pack Wl|Wr -> Bt[n][k] (transposed), hi/lo split ----------
__global__ void pack_bt_kernel(const float* __restrict__ Wl, const float* __restrict__ Wr,
                               __nv_bfloat16* __restrict__ bhi, __nv_bfloat16* __restrict__ blo,
                               int K, int Nhalf) {
    int idx = blockIdx.x * blockDim.x + threadIdx.x;
    int tot = 2 * Nhalf * K;
    if (idx < tot) {
        int n = idx / K, k = idx % K;
        float v = (n < Nhalf) ? Wl[(size_t)k * Nhalf + n] : Wr[(size_t)k * Nhalf + (n - Nhalf)];
        __nv_bfloat16 h = __float2bfloat16(v);
        bhi[idx] = h;
        blo[idx] = __float2bfloat16(v - __bfloat162float(h));
    }
}

// ---------------- async copy + ldmatrix helpers ----------------
__device__ __forceinline__ void cp16(void* sdst, const void* gsrc, int src_bytes) {
    uint32_t s = (uint32_t)__cvta_generic_to_shared(sdst);
    asm volatile("cp.async.cg.shared.global [%0], [%1], 16, %2;\n"
                 :: "r"(s), "l"(gsrc), "r"(src_bytes));
}
__device__ __forceinline__ void cp_commit() { asm volatile("cp.async.commit_group;\n"); }
__device__ __forceinline__ void cp_wait1() { asm volatile("cp.async.wait_group 1;\n"); }
__device__ __forceinline__ void cp_wait0() { asm volatile("cp.async.wait_group 0;\n"); }

__device__ __forceinline__ void ldsm4(uint32_t r[4], const void* p) {
    uint32_t a = (uint32_t)__cvta_generic_to_shared(p);
    asm volatile("ldmatrix.sync.aligned.m8n8.x4.shared.b16 {%0,%1,%2,%3}, [%4];\n"
                 : "=r"(r[0]), "=r"(r[1]), "=r"(r[2]), "=r"(r[3]) : "r"(a));
}

__device__ __forceinline__ void mma_bf16(float d[4], const uint32_t a[4], const uint32_t b[2]) {
    asm volatile(
        "mma.sync.aligned.m16n8k16.row.col.f32.bf16.bf16.f32 "
        "{%0,%1,%2,%3}, {%4,%5,%6,%7}, {%8,%9}, {%0,%1,%2,%3};\n"
        : "+f"(d[0]), "+f"(d[1]), "+f"(d[2]), "+f"(d[3])
        : "r"(a[0]), "r"(a[1]), "r"(a[2]), "r"(a[3]), "r"(b[0]), "r"(b[1]));
}

// ---- tensor-core GEMM, 3-term bf16 split, 3-stage cp.async, 1 sync/iter ----
template <int KCHUNKS>
__global__ __launch_bounds__(256, 2)
void mma_gemm_kernel(const __nv_bfloat16* __restrict__ Ahi, const __nv_bfloat16* __restrict__ Alo,
                     const __nv_bfloat16* __restrict__ Bhi, const __nv_bfloat16* __restrict__ Blo,
                     float* __restrict__ C0, float* __restrict__ C1,
                     int M, int ncut, int ld) {
    constexpr int K = KCHUNKS * 16;
    extern __shared__ __nv_bfloat16 sm[];
    // per-stage layout: As_hi | As_lo | Bs_hi | Bs_lo, each [128][24]
    __nv_bfloat16* stage_base[3] = { sm, sm + GEMM_STAGE_ELEMS, sm + 2 * GEMM_STAGE_ELEMS };

    int t = threadIdx.x;
    int lane = t & 31, wid = t >> 5;
    int wm = wid & 1, wn = wid >> 1;          // 2 x 4 warp grid
    int group = lane >> 2, tig = lane & 3;
    int m0 = blockIdx.y * 128, n0 = blockIdx.x * 128;

    int a_row = lane & 15;
    int a_col = ((lane >> 4) & 1) * 8;
    int b_row = ((lane >> 4) & 1) * 8 + (lane & 7);
    int b_col = ((lane >> 3) & 1) * 8;

    float acc[4][4][4];
#pragma unroll
    for (int i = 0; i < 4; i++)
#pragma unroll
        for (int j = 0; j < 4; j++)
#pragma unroll
            for (int q = 0; q < 4; q++) acc[i][j][q] = 0.f;

    int lrow = t >> 1, lkq = (t & 1) * 8;
    int grow = m0 + lrow;
    int abytes = (grow < M) ? 16 : 0;
    const __nv_bfloat16* pAhi = Ahi + (size_t)(grow < M ? grow : 0) * K + lkq;
    const __nv_bfloat16* pAlo = Alo + (size_t)(grow < M ? grow : 0) * K + lkq;
    const __nv_bfloat16* pBhi = Bhi + (size_t)(n0 + lrow) * K + lkq;
    const __nv_bfloat16* pBlo = Blo + (size_t)(n0 + lrow) * K + lkq;
    int lofs = lrow * 24 + lkq;

    // loader: one 16B cp.async into each of the 4 arrays of a stage
    auto load_stage = [&](int c, int st) {
        __nv_bfloat16* base = stage_base[st];
        int ko = c * 16;
        cp16(base + lofs,                 pAhi + ko, abytes);
        cp16(base + 3072 + lofs,          pAlo + ko, abytes);
        cp16(base + 6144 + lofs,          pBhi + ko, 16);
        cp16(base + 9216 + lofs,          pBlo + ko, 16);
        cp_commit();
    };

    load_stage(0, 0);
    if (KCHUNKS > 1) load_stage(1, 1);

#pragma unroll
    for (int c = 0; c < KCHUNKS; c++) {
        if (c + 1 < KCHUNKS) cp_wait1(); else cp_wait0();
        __syncthreads();
        if (c + 2 < KCHUNKS) load_stage(c + 2, (c + 2) % 3);

        __nv_bfloat16* base = stage_base[c % 3];
        __nv_bfloat16* as_hi = base;
        __nv_bfloat16* as_lo = base + 3072;
        __nv_bfloat16* bs_hi = base + 6144;
        __nv_bfloat16* bs_lo = base + 9216;

        uint32_t a_hi[4][4], a_lo[4][4];
#pragma unroll
        for (int mf = 0; mf < 4; mf++) {
            int r0 = wm * 64 + mf * 16;
            ldsm4(a_hi[mf], as_hi + (r0 + a_row) * 24 + a_col);
            ldsm4(a_lo[mf], as_lo + (r0 + a_row) * 24 + a_col);
        }
        uint32_t b_hi[2][4], b_lo[2][4];
#pragma unroll
        for (int p = 0; p < 2; p++) {
            int c0 = wn * 32 + p * 16;
            ldsm4(b_hi[p], bs_hi + (c0 + b_row) * 24 + b_col);
            ldsm4(b_lo[p], bs_lo + (c0 + b_row) * 24 + b_col);
        }
#pragma unroll
        for (int nf = 0; nf < 4; nf++) {
            const uint32_t* bh = &b_hi[nf >> 1][(nf & 1) * 2];
            const uint32_t* bl = &b_lo[nf >> 1][(nf & 1) * 2];
#pragma unroll
            for (int mf = 0; mf < 4; mf++) {
                mma_bf16(acc[mf][nf], a_hi[mf], bh);
                mma_bf16(acc[mf][nf], a_hi[mf], bl);
                mma_bf16(acc[mf][nf], a_lo[mf], bh);
            }
        }
    }

#pragma unroll
    for (int mf = 0; mf < 4; mf++) {
        int r = m0 + wm * 64 + mf * 16 + group;
#pragma unroll
        for (int nf = 0; nf < 4; nf++) {
            int cc = n0 + wn * 32 + nf * 8 + tig * 2;
            float* dst = C0;
            int ccol = cc;
            if (cc >= ncut) { dst = C1; ccol = cc - ncut; }
            if (r < M)
                *(float2*)&dst[(size_t)r * ld + ccol] = make_float2(acc[mf][nf][0], acc[mf][nf][1]);
            if (r + 8 < M)
                *(float2*)&dst[(size_t)(r + 8) * ld + ccol] = make_float2(acc[mf][nf][2], acc[mf][nf][3]);
        }
    }
}

#define LRELU(v) ((v) > 0.f ? (v) : 0.2f * (v))

// ---------------- Layer 1 GAT + fused bf16 split of hidden -----------------
__global__ void gat1_kernel(const float* __restrict__ att1, const float* __restrict__ b1,
                            const float* __restrict__ lng, const float* __restrict__ lnb,
                            int Nn) {
    int i = blockIdx.x;
    int t = threadIdx.x;          // 0..127
    int h = t >> 5;               // warp = head 0..3
    int l = t & 31;
    int s = l >> 3;               // edge slot 0..3
    int c = l & 7;                // channel group (8 ch each)
    __shared__ float sout[256];
    __shared__ float red[4];
    __shared__ float red2[4];

    const float* xrp = g_xr1 + (size_t)i * L1C + h * 64 + c * 8;
    float4 xr0 = ((const float4*)xrp)[0];
    float4 xr1 = ((const float4*)xrp)[1];
    const float* atp = att1 + h * 64 + c * 8;
    float4 at0 = ((const float4*)atp)[0];
    float4 at1 = ((const float4*)atp)[1];

    float acc[8] = {0.f, 0.f, 0.f, 0.f, 0.f, 0.f, 0.f, 0.f};
    float den = 0.f;
    int e0 = g_off[i], deg = g_off[i + 1] - e0;
    for (int base = 0; base < deg; base += 4) {
        int valid = (base + s) < deg;
        int j = valid ? __ldg(&g_src[e0 + base + s]) : 0;
        const float4* px = (const float4*)(g_xl1 + (size_t)j * L1C + h * 64 + c * 8);
        float4 xa0 = px[0], xa1 = px[1];
        float term = LRELU(xa0.x + xr0.x) * at0.x + LRELU(xa0.y + xr0.y) * at0.y
                   + LRELU(xa0.z + xr0.z) * at0.z + LRELU(xa0.w + xr0.w) * at0.w
                   + LRELU(xa1.x + xr1.x) * at1.x + LRELU(xa1.y + xr1.y) * at1.y
                   + LRELU(xa1.z + xr1.z) * at1.z + LRELU(xa1.w + xr1.w) * at1.w;
        term += __shfl_xor_sync(0xffffffffu, term, 1);
        term += __shfl_xor_sync(0xffffffffu, term, 2);
        term += __shfl_xor_sync(0xffffffffu, term, 4);
        float a = valid ? __expf(term) : 0.f;
        acc[0] += a * xa0.x; acc[1] += a * xa0.y; acc[2] += a * xa0.z; acc[3] += a * xa0.w;
        acc[4] += a * xa1.x; acc[5] += a * xa1.y; acc[6] += a * xa1.z; acc[7] += a * xa1.w;
        den += a;
    }
#pragma unroll
    for (int k = 0; k < 8; k++) {
        acc[k] += __shfl_xor_sync(0xffffffffu, acc[k], 8);
        acc[k] += __shfl_xor_sync(0xffffffffu, acc[k], 16);
    }
    den += __shfl_xor_sync(0xffffffffu, den, 8);
    den += __shfl_xor_sync(0xffffffffu, den, 16);
    float inv = 1.f / (den + 1e-16f);
    if (s == 0) {
#pragma unroll
        for (int k = 0; k < 8; k++) sout[h * 64 + c * 8 + k] = acc[k] * inv;
    }
    __syncthreads();

    int w = t >> 5, lane = t & 31;
    float val = 0.f;
    if (t < 64)
        val = 0.25f * (sout[t] + sout[t + 64] + sout[t + 128] + sout[t + 192]) + b1[t];

    float v = (t < 64) ? val : 0.f;
#pragma unroll
    for (int o = 16; o; o >>= 1) v += __shfl_xor_sync(0xffffffffu, v, o);
    if (lane == 0) red[w] = v;
    __syncthreads();
    float mu = (red[0] + red[1] + red[2] + red[3]) * (1.f / 64.f);
    float dd = (t < 64) ? (val - mu) : 0.f;
    float v2 = dd * dd;
#pragma unroll
    for (int o = 16; o; o >>= 1) v2 += __shfl_xor_sync(0xffffffffu, v2, o);
    if (lane == 0) red2[w] = v2;
    __syncthreads();
    float var = (red2[0] + red2[1] + red2[2] + red2[3]) * (1.f / 64.f);
    if (t < 64) {
        float y = dd * rsqrtf(var + 1e-5f) * lng[t] + lnb[t];
        float hv = fmaxf(y, 0.f);
        g_h[(size_t)i * HID + t] = hv;
        __nv_bfloat16 hb = __float2bfloat16(hv);
        g_ahi[(size_t)i * HID + t] = hb;
        g_alo[(size_t)i * HID + t] = __float2bfloat16(hv - __bfloat162float(hb));
    }
}

// ---------------- Layer 2 GAT: warp per node, 4 edges/warp, LN fused -------
__global__ void gat2_kernel(const float* __restrict__ att2, const float* __restrict__ b2,
                            const float* __restrict__ lng, const float* __restrict__ lnb,
                            float* __restrict__ out, int Nn) {
    int w = threadIdx.x >> 5, l = threadIdx.x & 31;
    int i = blockIdx.x * 4 + w;
    if (i >= Nn) return;
    int s = l >> 3;
    int c = l & 7;
    const float* xl2 = g_xr1;                               // overlay
    const float* xr2 = g_xr1 + (size_t)NMAX * OUTD;         // overlay

    const float* xrp = xr2 + (size_t)i * OUTD + c * 8;
    float4 xr0 = ((const float4*)xrp)[0];
    float4 xr1 = ((const float4*)xrp)[1];
    const float* atp = att2 + c * 8;
    float4 at0 = ((const float4*)atp)[0];
    float4 at1 = ((const float4*)atp)[1];

    float acc[8] = {0.f, 0.f, 0.f, 0.f, 0.f, 0.f, 0.f, 0.f};
    float den = 0.f;
    int e0 = g_off[i], deg = g_off[i + 1] - e0;
    for (int base = 0; base < deg; base += 4) {
        int valid = (base + s) < deg;
        int j = valid ? __ldg(&g_src[e0 + base + s]) : 0;
        const float4* px = (const float4*)(xl2 + (size_t)j * OUTD + c * 8);
        float4 xa0 = px[0], xa1 = px[1];
        float term = LRELU(xa0.x + xr0.x) * at0.x + LRELU(xa0.y + xr0.y) * at0.y
                   + LRELU(xa0.z + xr0.z) * at0.z + LRELU(xa0.w + xr0.w) * at0.w
                   + LRELU(xa1.x + xr1.x) * at1.x + LRELU(xa1.y + xr1.y) * at1.y
                   + LRELU(xa1.z + xr1.z) * at1.z + LRELU(xa1.w + xr1.w) * at1.w;
        term += __shfl_xor_sync(0xffffffffu, term, 1);
        term += __shfl_xor_sync(0xffffffffu, term, 2);
        term += __shfl_xor_sync(0xffffffffu, term, 4);
        float a = valid ? __expf(term) : 0.f;
        acc[0] += a * xa0.x; acc[1] += a * xa0.y; acc[2] += a * xa0.z; acc[3] += a * xa0.w;
        acc[4] += a * xa1.x; acc[5] += a * xa1.y; acc[6] += a * xa1.z; acc[7] += a * xa1.w;
        den += a;
    }
#pragma unroll
    for (int k = 0; k < 8; k++) {
        acc[k] += __shfl_xor_sync(0xffffffffu, acc[k], 8);
        acc[k] += __shfl_xor_sync(0xffffffffu, acc[k], 16);
    }
    den += __shfl_xor_sync(0xffffffffu, den, 8);
    den += __shfl_xor_sync(0xffffffffu, den, 16);
    float inv = 1.f / (den + 1e-16f);

    const float* bp = b2 + c * 8;
    float4 bb0 = ((const float4*)bp)[0];
    float4 bb1 = ((const float4*)bp)[1];
    float v[8];
    v[0] = acc[0] * inv + bb0.x; v[1] = acc[1] * inv + bb0.y;
    v[2] = acc[2] * inv + bb0.z; v[3] = acc[3] * inv + bb0.w;
    v[4] = acc[4] * inv + bb1.x; v[5] = acc[5] * inv + bb1.y;
    v[6] = acc[6] * inv + bb1.z; v[7] = acc[7] * inv + bb1.w;

    float sum = v[0] + v[1] + v[2] + v[3] + v[4] + v[5] + v[6] + v[7];
#pragma unroll
    for (int o = 16; o; o >>= 1) sum += __shfl_xor_sync(0xffffffffu, sum, o);
    float mu = sum * (1.f / 256.f);
    float q = 0.f;
    float d[8];
#pragma unroll
    for (int k = 0; k < 8; k++) { d[k] = v[k] - mu; q += d[k] * d[k]; }
#pragma unroll
    for (int o = 16; o; o >>= 1) q += __shfl_xor_sync(0xffffffffu, q, o);
    float var = q * (1.f / 256.f);
    float r = rsqrtf(var + 1e-5f);
    if (s == 0) {
        const float* gp = lng + c * 8;
        const float* np = lnb + c * 8;
        float4 gg0 = ((const float4*)gp)[0], gg1 = ((const float4*)gp)[1];
        float4 nn0 = ((const float4*)np)[0], nn1 = ((const float4*)np)[1];
        float4 o0, o1;
        o0.x = d[0] * r * gg0.x + nn0.x; o0.y = d[1] * r * gg0.y + nn0.y;
        o0.z = d[2] * r * gg0.z + nn0.z; o0.w = d[3] * r * gg0.w + nn0.w;
        o1.x = d[4] * r * gg1.x + nn1.x; o1.y = d[5] * r * gg1.y + nn1.y;
        o1.z = d[6] * r * gg1.z + nn1.z; o1.w = d[7] * r * gg1.w + nn1.w;
        float* op = out + (size_t)i * OUTD + c * 8;
        ((float4*)op)[0] = o0;
        ((float4*)op)[1] = o1;
    }
}

// ---------------- launch ----------------
extern "C" void kernel_launch(void* const* d_in, const int* in_sizes, int n_in,
                              void* d_out, int out_size) {
    const float* x    = (const float*)d_in[0];
    const int*   ei   = (const int*)d_in[1];
    const float* W1l  = (const float*)d_in[2];
    const float* W1r  = (const float*)d_in[3];
    const float* att1 = (const float*)d_in[4];
    const float* b1   = (const float*)d_in[5];
    const float* ln1g = (const float*)d_in[6];
    const float* ln1b = (const float*)d_in[7];
    const float* W2l  = (const float*)d_in[8];
    const float* W2r  = (const float*)d_in[9];
    const float* att2 = (const float*)d_in[10];
    const float* b2   = (const float*)d_in[11];
    const float* ln2g = (const float*)d_in[12];
    const float* ln2b = (const float*)d_in[13];
    float* out = (float*)d_out;

    int N = in_sizes[0] / IN_DIM;
    int E = in_sizes[1] / 2;
    if (N > NMAX) N = NMAX;
    if (E > EMAX) E = EMAX;
    int ETOT_RT = E + N;
    int nscan = (N + SCAN_BLK - 1) / SCAN_BLK;

    float *p_xl1, *p_xr1, *p_h;
    __nv_bfloat16 *p_ahi, *p_alo, *p_bhi, *p_blo, *p_bhi2, *p_blo2;
    cudaGetSymbolAddress((void**)&p_xl1, g_xl1);
    cudaGetSymbolAddress((void**)&p_xr1, g_xr1);
    cudaGetSymbolAddress((void**)&p_h,   g_h);
    cudaGetSymbolAddress((void**)&p_ahi, g_ahi);
    cudaGetSymbolAddress((void**)&p_alo, g_alo);
    cudaGetSymbolAddress((void**)&p_bhi, g_bhi);
    cudaGetSymbolAddress((void**)&p_blo, g_blo);
    cudaGetSymbolAddress((void**)&p_bhi2, g_bhi2);
    cudaGetSymbolAddress((void**)&p_blo2, g_blo2);
    float* p_xl2 = p_xr1;                              // overlay for layer 2
    float* p_xr2 = p_xr1 + (size_t)NMAX * OUTD;

    // opt-in to 72KB dynamic smem for the GEMM kernels (idempotent)
    cudaFuncSetAttribute(mma_gemm_kernel<16>, cudaFuncAttributeMaxDynamicSharedMemorySize, GEMM_SMEM_BYTES);
    cudaFuncSetAttribute(mma_gemm_kernel<4>,  cudaFuncAttributeMaxDynamicSharedMemorySize, GEMM_SMEM_BYTES);

    // streams/events created once (first call is uncaptured correctness run)
    static cudaStream_t s2 = nullptr;
    static cudaEvent_t ev_fork = nullptr, ev_g1 = nullptr;
    if (!s2) {
        cudaStreamCreateWithFlags(&s2, cudaStreamNonBlocking);
        cudaEventCreateWithFlags(&ev_fork, cudaEventDisableTiming);
        cudaEventCreateWithFlags(&ev_g1, cudaEventDisableTiming);
    }

    // fork: s2 joins the (possibly capturing) default stream
    cudaEventRecord(ev_fork, 0);
    cudaStreamWaitEvent(s2, ev_fork, 0);

    // ---- stream s2: layer-1 GEMM chain (independent of graph) ----
    {
        int n4 = N * IN_DIM / 4;
        conv_split_kernel<<<(n4 + 255) / 256, 256, 0, s2>>>(x, p_ahi, p_alo, n4);
        pack_bt_kernel<<<(512 * 256 + 255) / 256, 256, 0, s2>>>(W1l, W1r, p_bhi, p_blo, 256, 256);
        pack_bt_kernel<<<(128 * 64 + 255) / 256, 256, 0, s2>>>(W2l, W2r, p_bhi2, p_blo2, 64, 64);
        dim3 grid(512 / 128, (N + 127) / 128);
        mma_gemm_kernel<16><<<grid, 256, GEMM_SMEM_BYTES, s2>>>(p_ahi, p_alo, p_bhi, p_blo,
                                                                p_xl1, p_xr1, N, 256, 256);
        cudaEventRecord(ev_g1, s2);
    }

    // ---- default stream: CSR build (runs concurrently) ----
    zero_deg_kernel<<<(N + 256) / 256, 256>>>(N);
    hist_kernel<<<(ETOT_RT + 255) / 256, 256>>>(ei, E, N);
    scan1_kernel<<<nscan, SCAN_BLK>>>(N);
    scan2_kernel<<<1, 64>>>(nscan, N);
    scan3_kernel<<<nscan, SCAN_BLK>>>(N);
    scatter_kernel<<<(ETOT_RT + 255) / 256, 256>>>(ei, E, N);

    // join: gat1 needs CSR (default) + GEMM1 (s2)
    cudaStreamWaitEvent(0, ev_g1, 0);

    // Layer 1 edge pass (+ fused bf16 split of hidden into g_ahi/g_alo)
    gat1_kernel<<<N, 128>>>(att1, b1, ln1g, ln1b, N);

    // Layer 2 GEMM: [N,64] x [64,128] -> xl2 | xr2 (overlay)
    {
        dim3 grid(1, (N + 127) / 128);
        mma_gemm_kernel<4><<<grid, 256, GEMM_SMEM_BYTES>>>(p_ahi, p_alo, p_bhi2, p_blo2,
                                                           p_xl2, p_xr2, N, 64, 64);
    }

    // Layer 2 edge + softmax + aggregate + bias + LN -> out
    gat2_kernel<<<(N + 3) / 4, 128>>>(att2, b2, ln2g, ln2b, out, N);
}